// round 4
// baseline (speedup 1.0000x reference)
#include <cuda_runtime.h>
#include <math.h>
#include <stddef.h>

// ---------------------------------------------------------------------------
// Problem constants (fixed by the dataset)
// ---------------------------------------------------------------------------
constexpr int BATCH  = 8;
constexpr int DIN    = 512;
constexpr int DINNER = 256;
constexpr int NSTATE = 16;
constexpr int L1 = 1024, L2 = 256, L3 = 64;

// ---------------------------------------------------------------------------
// Scratch (single __device__ buffer; no allocations anywhere)
// ---------------------------------------------------------------------------
constexpr size_t SZ_XZ   = (size_t)BATCH * 512 * 1024;
constexpr size_t SZ_F1   = (size_t)BATCH * 256 * 1024;
constexpr size_t SZ_F2   = (size_t)BATCH * 256 * 256;
constexpr size_t SZ_F3   = (size_t)BATCH * 256 * 64;
constexpr size_t SZ_COL2 = (size_t)BATCH * 1024 * 256;
constexpr size_t SZ_COL3 = (size_t)BATCH * 1024 * 64;
constexpr size_t SZ_XD1  = (size_t)BATCH * 1024 * 40;
constexpr size_t SZ_XD2  = (size_t)BATCH * 256 * 40;
constexpr size_t SZ_XD3  = (size_t)BATCH * 64 * 40;
constexpr size_t SZ_Y1   = (size_t)BATCH * 1024 * 256;
constexpr size_t SZ_Y2   = (size_t)BATCH * 256 * 256;
constexpr size_t SZ_Y3   = (size_t)BATCH * 64 * 256;

constexpr size_t OFF_XZ    = 0;
constexpr size_t OFF_F1    = OFF_XZ   + SZ_XZ;
constexpr size_t OFF_F2    = OFF_F1   + SZ_F1;
constexpr size_t OFF_F3    = OFF_F2   + SZ_F2;
constexpr size_t OFF_COL2  = OFF_F3   + SZ_F3;
constexpr size_t OFF_COL3  = OFF_COL2 + SZ_COL2;
constexpr size_t OFF_XD1A  = OFF_COL3 + SZ_COL3;
constexpr size_t OFF_XD1B  = OFF_XD1A + SZ_XD1;
constexpr size_t OFF_XD2   = OFF_XD1B + SZ_XD1;
constexpr size_t OFF_XD3   = OFF_XD2  + SZ_XD2;
constexpr size_t OFF_YF1   = OFF_XD3  + SZ_XD3;
constexpr size_t OFF_YR1   = OFF_YF1  + SZ_Y1;
constexpr size_t OFF_YF2   = OFF_YR1  + SZ_Y1;
constexpr size_t OFF_YR2   = OFF_YF2  + SZ_Y2;
constexpr size_t OFF_YF3   = OFF_YR2  + SZ_Y2;
constexpr size_t OFF_YR3   = OFF_YF3  + SZ_Y3;
constexpr size_t OFF_Y3O   = OFF_YR3  + SZ_Y3;
constexpr size_t OFF_Y2O   = OFF_Y3O  + SZ_Y3;
constexpr size_t OFF_Y1O   = OFF_Y2O  + SZ_Y2;
constexpr size_t OFF_GATED = OFF_Y1O  + SZ_Y1;
constexpr size_t SCRATCH_TOTAL = OFF_GATED + SZ_F1;

__device__ float g_scratch[SCRATCH_TOTAL];

// ---------------------------------------------------------------------------
// Generic tiled SGEMM: C[m,n] = sum_k A[m,k]*B[k,n] (+bias[m])
// A row-major [M,K] (lda), B row-major [K,N] (ldb), batched over grid.z on B/C.
// C written at Cp[m*ldcm + n*ldcn] (lets us emit transposed outputs).
// Requires K % 8 == 0 (true for all call sites: 512/256/1024).
// ---------------------------------------------------------------------------
#define GBM 128
#define GBN 128
#define GBK 8
#define GTM 8
#define GTN 8

__global__ __launch_bounds__(256)
void sgemm_kernel(const float* __restrict__ A, const float* __restrict__ B,
                  float* __restrict__ C, const float* __restrict__ bias,
                  int M, int N, int K, int lda, int ldb,
                  long long strideB, long long strideC,
                  int ldcm, int ldcn)
{
    __shared__ float As[GBK][GBM];
    __shared__ float Bs[GBK][GBN];

    const int tid = threadIdx.x;
    const int tx = tid & 15;
    const int ty = tid >> 4;
    const int m0 = blockIdx.y * GBM;
    const int n0 = blockIdx.x * GBN;
    const float* Bp = B + (size_t)blockIdx.z * (size_t)strideB;
    float* Cp = C + (size_t)blockIdx.z * (size_t)strideC;

    float acc[GTM][GTN];
#pragma unroll
    for (int i = 0; i < GTM; i++)
#pragma unroll
        for (int j = 0; j < GTN; j++) acc[i][j] = 0.f;

    const int arow = tid >> 1;        // 0..127
    const int acol = (tid & 1) * 4;   // 0 or 4
    const int brow = tid >> 5;        // 0..7
    const int bcol = (tid & 31) * 4;  // 0..124

    for (int k0 = 0; k0 < K; k0 += GBK) {
        // --- load A tile (128 x 8), store transposed As[k][m] ---
        {
            const int m = m0 + arow;
            if (m < M) {
                float4 v = *reinterpret_cast<const float4*>(A + (size_t)m * lda + k0 + acol);
                As[acol + 0][arow] = v.x;
                As[acol + 1][arow] = v.y;
                As[acol + 2][arow] = v.z;
                As[acol + 3][arow] = v.w;
            } else {
                As[acol + 0][arow] = 0.f;
                As[acol + 1][arow] = 0.f;
                As[acol + 2][arow] = 0.f;
                As[acol + 3][arow] = 0.f;
            }
        }
        // --- load B tile (8 x 128) ---
        {
            const int n = n0 + bcol;
            const float* bp = Bp + (size_t)(k0 + brow) * ldb + n;
            if (n + 4 <= N) {
                *reinterpret_cast<float4*>(&Bs[brow][bcol]) =
                    *reinterpret_cast<const float4*>(bp);
            } else {
#pragma unroll
                for (int i = 0; i < 4; i++)
                    Bs[brow][bcol + i] = (n + i < N) ? bp[i] : 0.f;
            }
        }
        __syncthreads();

#pragma unroll
        for (int kk = 0; kk < GBK; kk++) {
            const float4 a0 = *reinterpret_cast<const float4*>(&As[kk][ty * GTM]);
            const float4 a1 = *reinterpret_cast<const float4*>(&As[kk][ty * GTM + 4]);
            const float4 b0 = *reinterpret_cast<const float4*>(&Bs[kk][tx * GTN]);
            const float4 b1 = *reinterpret_cast<const float4*>(&Bs[kk][tx * GTN + 4]);
            const float av[8] = {a0.x, a0.y, a0.z, a0.w, a1.x, a1.y, a1.z, a1.w};
            const float bv[8] = {b0.x, b0.y, b0.z, b0.w, b1.x, b1.y, b1.z, b1.w};
#pragma unroll
            for (int i = 0; i < GTM; i++)
#pragma unroll
                for (int j = 0; j < GTN; j++)
                    acc[i][j] += av[i] * bv[j];
        }
        __syncthreads();
    }

#pragma unroll
    for (int i = 0; i < GTM; i++) {
        const int m = m0 + ty * GTM + i;
        if (m >= M) continue;
        const float bv = bias ? bias[m] : 0.f;
#pragma unroll
        for (int j = 0; j < GTN; j++) {
            const int n = n0 + tx * GTN + j;
            if (n < N)
                Cp[(size_t)m * ldcm + (size_t)n * ldcn] = acc[i][j] + bv;
        }
    }
}

// ---------------------------------------------------------------------------
// im2col for 2x2/stride-2 conv: src [B][C][Hs][Ws] -> dst [B][C*4][Ho*Wo]
// ---------------------------------------------------------------------------
__global__ void im2col_k(const float* __restrict__ src, float* __restrict__ dst,
                         int C, int Hs, int Ws)
{
    const int Ho = Hs >> 1, Wo = Ws >> 1;
    const int P = Ho * Wo;
    const int nTot = BATCH * C * 4 * P;
    const int idx = blockIdx.x * blockDim.x + threadIdx.x;
    if (idx >= nTot) return;
    const int n = idx % P;
    const int k = (idx / P) % (C * 4);
    const int b = idx / (P * C * 4);
    const int c = k >> 2;
    const int i = (k >> 1) & 1;
    const int j = k & 1;
    const int h = n / Wo;
    const int w = n % Wo;
    dst[idx] = src[(((size_t)b * C + c) * Hs + 2 * h + i) * Ws + 2 * w + j];
}

// ---------------------------------------------------------------------------
// Selective-scan kernel: 6 scans in one launch (blockIdx.y = scan id).
// One thread per (b,d). xd layout [b][L][40] (dts|Bs|Cs). x layout [b][d][L].
// Output y [b][l][d] = sum_n h*C + x*Dv (pre-LayerNorm). dir=1 handles the
// flipped scan (reads & writes at L-1-t, so the buffer already holds
// flip(ssm(flip(x))), valid since LN commutes with flip).
// ---------------------------------------------------------------------------
struct ScanCfg {
    const float* x;
    const float* xd;
    float* y;
    const float* dtw;
    const float* dtb;
    const float* Al;
    const float* Dv;
    int L;
    int dir;
};
struct ScanArgs { ScanCfg c[6]; };

__global__ __launch_bounds__(128)
void scan_kernel(ScanArgs args)
{
    const ScanCfg cfg = args.c[blockIdx.y];
    const int gid = blockIdx.x * 128 + threadIdx.x;   // 0..2047
    const int b = gid >> 8;
    const int d = gid & 255;
    const int L = cfg.L;
    const int dir = cfg.dir;

    float dtw_r[8];
#pragma unroll
    for (int i = 0; i < 8; i++) dtw_r[i] = cfg.dtw[d * 8 + i];
    const float dtb_r = cfg.dtb[d];
    const float Dv_r  = cfg.Dv[d];

    float A_r[16];
    bool pw = true;
#pragma unroll
    for (int n = 0; n < 16; n++) {
        A_r[n] = -expf(cfg.Al[d * 16 + n]);
        pw = pw && (fabsf(A_r[n] + (float)(n + 1)) <= 1e-4f * (float)(n + 1));
    }

    const float* xrow = cfg.x + ((size_t)b * 256 + d) * (size_t)L;
    const float* xdb  = cfg.xd + (size_t)b * L * 40;
    float* yb = cfg.y + (size_t)b * L * 256 + d;

    float h[16];
#pragma unroll
    for (int n = 0; n < 16; n++) h[n] = 0.f;

    if (pw) {
        // A[d][n] == -(n+1): one exp per step, powers by multiply tree.
        for (int t = 0; t < L; t++) {
            const int l = dir ? (L - 1 - t) : t;
            const float4* q = reinterpret_cast<const float4*>(xdb + (size_t)l * 40);
            const float4 d0 = q[0], d1 = q[1];
            const float4 B0 = q[2], B1 = q[3], B2 = q[4], B3 = q[5];
            const float4 C0 = q[6], C1 = q[7], C2 = q[8], C3 = q[9];
            float pre = dtb_r
                + d0.x * dtw_r[0] + d0.y * dtw_r[1] + d0.z * dtw_r[2] + d0.w * dtw_r[3]
                + d1.x * dtw_r[4] + d1.y * dtw_r[5] + d1.z * dtw_r[6] + d1.w * dtw_r[7];
            const float delta = (pre > 20.f) ? pre : log1pf(__expf(pre));
            const float xv = xrow[l];
            const float dx = delta * xv;
            const float p1 = __expf(-delta);
            const float p2 = p1 * p1, p3 = p2 * p1, p4 = p2 * p2;
            const float p5 = p4 * p1, p6 = p4 * p2, p7 = p4 * p3, p8 = p4 * p4;
            const float p9 = p8 * p1, p10 = p8 * p2, p11 = p8 * p3, p12 = p8 * p4;
            const float p13 = p8 * p5, p14 = p8 * p6, p15 = p8 * p7, p16 = p8 * p8;
            const float rr[16] = {p1,p2,p3,p4,p5,p6,p7,p8,p9,p10,p11,p12,p13,p14,p15,p16};
            const float Bv[16] = {B0.x,B0.y,B0.z,B0.w,B1.x,B1.y,B1.z,B1.w,
                                  B2.x,B2.y,B2.z,B2.w,B3.x,B3.y,B3.z,B3.w};
            const float Cv[16] = {C0.x,C0.y,C0.z,C0.w,C1.x,C1.y,C1.z,C1.w,
                                  C2.x,C2.y,C2.z,C2.w,C3.x,C3.y,C3.z,C3.w};
            float yacc = xv * Dv_r;
#pragma unroll
            for (int n = 0; n < 16; n++) {
                h[n] = h[n] * rr[n] + dx * Bv[n];
                yacc += h[n] * Cv[n];
            }
            yb[(size_t)l * 256] = yacc;
        }
    } else {
        // General path (data-independent correctness guarantee).
        for (int t = 0; t < L; t++) {
            const int l = dir ? (L - 1 - t) : t;
            const float4* q = reinterpret_cast<const float4*>(xdb + (size_t)l * 40);
            const float4 d0 = q[0], d1 = q[1];
            const float4 B0 = q[2], B1 = q[3], B2 = q[4], B3 = q[5];
            const float4 C0 = q[6], C1 = q[7], C2 = q[8], C3 = q[9];
            float pre = dtb_r
                + d0.x * dtw_r[0] + d0.y * dtw_r[1] + d0.z * dtw_r[2] + d0.w * dtw_r[3]
                + d1.x * dtw_r[4] + d1.y * dtw_r[5] + d1.z * dtw_r[6] + d1.w * dtw_r[7];
            const float delta = (pre > 20.f) ? pre : log1pf(__expf(pre));
            const float xv = xrow[l];
            const float dx = delta * xv;
            const float Bv[16] = {B0.x,B0.y,B0.z,B0.w,B1.x,B1.y,B1.z,B1.w,
                                  B2.x,B2.y,B2.z,B2.w,B3.x,B3.y,B3.z,B3.w};
            const float Cv[16] = {C0.x,C0.y,C0.z,C0.w,C1.x,C1.y,C1.z,C1.w,
                                  C2.x,C2.y,C2.z,C2.w,C3.x,C3.y,C3.z,C3.w};
            float yacc = xv * Dv_r;
#pragma unroll
            for (int n = 0; n < 16; n++) {
                h[n] = h[n] * __expf(delta * A_r[n]) + dx * Bv[n];
                yacc += h[n] * Cv[n];
            }
            yb[(size_t)l * 256] = yacc;
        }
    }
}

// ---------------------------------------------------------------------------
// Combine: out[b,l,:] = LN(yf)*gf+bef + LN(yr)*gr+ber + up2(src)
// Block = 256 threads (one per d), grid = B*L.
// ---------------------------------------------------------------------------
__device__ __forceinline__ float4 warpReduce4(float4 v)
{
#pragma unroll
    for (int o = 16; o > 0; o >>= 1) {
        v.x += __shfl_xor_sync(0xffffffffu, v.x, o);
        v.y += __shfl_xor_sync(0xffffffffu, v.y, o);
        v.z += __shfl_xor_sync(0xffffffffu, v.z, o);
        v.w += __shfl_xor_sync(0xffffffffu, v.w, o);
    }
    return v;
}

__global__ __launch_bounds__(256)
void combine_kernel(const float* __restrict__ yf, const float* __restrict__ yr,
                    const float* __restrict__ gf, const float* __restrict__ bef,
                    const float* __restrict__ gr, const float* __restrict__ ber,
                    const float* __restrict__ up, float* __restrict__ out,
                    int L, int wgrid)
{
    __shared__ float4 red[8];
    const int bl = blockIdx.x;              // b*L + l
    const int d  = threadIdx.x;             // 0..255
    const size_t base = (size_t)bl * 256;

    const float vf = yf[base + d];
    const float vr = yr[base + d];

    float4 s = warpReduce4(make_float4(vf, vf * vf, vr, vr * vr));
    const int warp = threadIdx.x >> 5;
    const int lane = threadIdx.x & 31;
    if (lane == 0) red[warp] = s;
    __syncthreads();
    if (warp == 0) {
        float4 t = (lane < 8) ? red[lane] : make_float4(0.f, 0.f, 0.f, 0.f);
#pragma unroll
        for (int o = 4; o > 0; o >>= 1) {
            t.x += __shfl_xor_sync(0xffffffffu, t.x, o);
            t.y += __shfl_xor_sync(0xffffffffu, t.y, o);
            t.z += __shfl_xor_sync(0xffffffffu, t.z, o);
            t.w += __shfl_xor_sync(0xffffffffu, t.w, o);
        }
        if (lane == 0) red[0] = t;
    }
    __syncthreads();
    const float4 tot = red[0];

    const float inv = 1.f / 256.f;
    const float muf = tot.x * inv;
    const float varf = tot.y * inv - muf * muf;
    const float mur = tot.z * inv;
    const float varr = tot.w * inv - mur * mur;

    const float of = (vf - muf) * rsqrtf(varf + 1e-5f) * gf[d] + bef[d];
    const float orr = (vr - mur) * rsqrtf(varr + 1e-5f) * gr[d] + ber[d];

    float u = 0.f;
    if (up) {
        const int b = bl / L, l = bl % L;
        const int hh = l / wgrid, ww = l % wgrid;
        const int lsrc = (hh >> 1) * (wgrid >> 1) + (ww >> 1);
        u = up[((size_t)b * (L >> 2) + lsrc) * 256 + d];
    }
    out[base + d] = of + orr + u;
}

// ---------------------------------------------------------------------------
// Gate: gated[b][c][p] = y1o[b][p][c] * silu(xz[b][256+c][p])
// 32x32 SMEM transpose tiles. grid (32, 8, BATCH), block (32, 8).
// ---------------------------------------------------------------------------
__global__ __launch_bounds__(256)
void gate_kernel(const float* __restrict__ y1o, const float* __restrict__ xz,
                 float* __restrict__ gated)
{
    __shared__ float tile[32][33];
    const int b = blockIdx.z;
    const int p0 = blockIdx.x * 32;
    const int c0 = blockIdx.y * 32;
    const int tx = threadIdx.x;   // 0..31
    const int ty = threadIdx.y;   // 0..7

#pragma unroll
    for (int k = 0; k < 4; k++) {
        const int p = p0 + ty + k * 8;
        tile[ty + k * 8][tx] = y1o[((size_t)b * 1024 + p) * 256 + c0 + tx];
    }
    __syncthreads();
#pragma unroll
    for (int k = 0; k < 4; k++) {
        const int c = c0 + ty + k * 8;
        const int p = p0 + tx;
        const float z = xz[((size_t)b * 512 + 256 + c) * 1024 + p];
        const float sz = z / (1.f + __expf(-z));
        gated[((size_t)b * 256 + c) * 1024 + p] = tile[tx][ty + k * 8] * sz;
    }
}

// ---------------------------------------------------------------------------
// Launcher
// ---------------------------------------------------------------------------
extern "C" void kernel_launch(void* const* d_in, const int* in_sizes, int n_in,
                              void* d_out, int out_size)
{
    const float* input_f = (const float*)d_in[0];
    const float* in_w    = (const float*)d_in[1];
    const float* in_b    = (const float*)d_in[2];
    const float* c1_w    = (const float*)d_in[3];
    const float* c1_b    = (const float*)d_in[4];
    const float* c2_w    = (const float*)d_in[5];
    const float* c2_b    = (const float*)d_in[6];
    const float* c3_w    = (const float*)d_in[7];
    const float* c3_b    = (const float*)d_in[8];
    const float* out_w   = (const float*)d_in[9];
    const float* out_b   = (const float*)d_in[10];
    // param sets: 11..17 (p1), 18..24 (p2), 25..31 (p3)
    const float* xw1  = (const float*)d_in[11];
    const float* dtw1 = (const float*)d_in[12];
    const float* dtb1 = (const float*)d_in[13];
    const float* Al1  = (const float*)d_in[14];
    const float* Dv1  = (const float*)d_in[15];
    const float* g1   = (const float*)d_in[16];
    const float* be1  = (const float*)d_in[17];
    const float* xw2  = (const float*)d_in[18];
    const float* dtw2 = (const float*)d_in[19];
    const float* dtb2 = (const float*)d_in[20];
    const float* Al2  = (const float*)d_in[21];
    const float* Dv2  = (const float*)d_in[22];
    const float* g2   = (const float*)d_in[23];
    const float* be2  = (const float*)d_in[24];
    const float* xw3  = (const float*)d_in[25];
    const float* dtw3 = (const float*)d_in[26];
    const float* dtb3 = (const float*)d_in[27];
    const float* Al3  = (const float*)d_in[28];
    const float* Dv3  = (const float*)d_in[29];
    const float* g3   = (const float*)d_in[30];
    const float* be3  = (const float*)d_in[31];
    (void)in_sizes; (void)n_in; (void)out_size;

    float* scratch = nullptr;
    cudaGetSymbolAddress((void**)&scratch, g_scratch);

    float* xz   = scratch + OFF_XZ;
    float* f1   = scratch + OFF_F1;
    float* f2   = scratch + OFF_F2;
    float* f3   = scratch + OFF_F3;
    float* col2 = scratch + OFF_COL2;
    float* col3 = scratch + OFF_COL3;
    float* xd1a = scratch + OFF_XD1A;
    float* xd1b = scratch + OFF_XD1B;
    float* xd2  = scratch + OFF_XD2;
    float* xd3  = scratch + OFF_XD3;
    float* yf1  = scratch + OFF_YF1;
    float* yr1  = scratch + OFF_YR1;
    float* yf2  = scratch + OFF_YF2;
    float* yr2  = scratch + OFF_YR2;
    float* yf3  = scratch + OFF_YF3;
    float* yr3  = scratch + OFF_YR3;
    float* y3o  = scratch + OFF_Y3O;
    float* y2o  = scratch + OFF_Y2O;
    float* y1o  = scratch + OFF_Y1O;
    float* gated = scratch + OFF_GATED;
    float* outp = (float*)d_out;

    // 1) in-projection: xz[b][o][p], M=512,N=1024,K=512
    sgemm_kernel<<<dim3(8, 4, BATCH), 256>>>(in_w, input_f, xz, in_b,
        512, 1024, 512, 512, 1024, 512LL * 1024, 512LL * 1024, 1024, 1);

    // 2) c1: f1 = conv1x1(x): M=256,N=1024,K=256 (B = first 256 rows of xz)
    sgemm_kernel<<<dim3(8, 2, BATCH), 256>>>(c1_w, xz, f1, c1_b,
        256, 1024, 256, 256, 1024, 512LL * 1024, 256LL * 1024, 1024, 1);

    // 3) f2 = conv2s2(f1): im2col + GEMM (K = 256*4)
    im2col_k<<<(BATCH * 256 * 4 * 256 + 255) / 256, 256>>>(f1, col2, 256, 32, 32);
    sgemm_kernel<<<dim3(2, 2, BATCH), 256>>>(c2_w, col2, f2, c2_b,
        256, 256, 1024, 1024, 256, 1024LL * 256, 256LL * 256, 256, 1);

    // 4) f3 = conv2s2(f2)
    im2col_k<<<(BATCH * 256 * 4 * 64 + 255) / 256, 256>>>(f2, col3, 256, 16, 16);
    sgemm_kernel<<<dim3(1, 2, BATCH), 256>>>(c3_w, col3, f3, c3_b,
        256, 64, 1024, 1024, 64, 1024LL * 64, 256LL * 64, 64, 1);

    // 5) xd projections -> [b][L][40]  (C[k,l] written transposed: ldcm=1, ldcn=40)
    sgemm_kernel<<<dim3(8, 1, BATCH), 256>>>(xw1, f1, xd1a, nullptr,
        40, 1024, 256, 256, 1024, 256LL * 1024, 1024LL * 40, 1, 40);
    sgemm_kernel<<<dim3(8, 1, BATCH), 256>>>(xw2, f1, xd1b, nullptr,
        40, 1024, 256, 256, 1024, 256LL * 1024, 1024LL * 40, 1, 40);
    sgemm_kernel<<<dim3(2, 1, BATCH), 256>>>(xw2, f2, xd2, nullptr,
        40, 256, 256, 256, 256, 256LL * 256, 256LL * 40, 1, 40);
    sgemm_kernel<<<dim3(1, 1, BATCH), 256>>>(xw3, f3, xd3, nullptr,
        40, 64, 256, 256, 64, 256LL * 64, 64LL * 40, 1, 40);

    // 6) all six selective scans in one launch
    ScanArgs sa;
    sa.c[0] = {f1, xd1a, yf1, dtw1, dtb1, Al1, Dv1, L1, 0};  // level1 forward (params1)
    sa.c[1] = {f1, xd1b, yr1, dtw2, dtb2, Al2, Dv2, L1, 1};  // level1 reverse (params2! — ref quirk)
    sa.c[2] = {f2, xd2,  yf2, dtw2, dtb2, Al2, Dv2, L2, 0};
    sa.c[3] = {f2, xd2,  yr2, dtw2, dtb2, Al2, Dv2, L2, 1};
    sa.c[4] = {f3, xd3,  yf3, dtw3, dtb3, Al3, Dv3, L3, 0};
    sa.c[5] = {f3, xd3,  yr3, dtw3, dtb3, Al3, Dv3, L3, 1};
    scan_kernel<<<dim3(16, 6), 128>>>(sa);

    // 7) combine (LayerNorm per direction + sum + upsample-add), bottom-up
    combine_kernel<<<BATCH * L3, 256>>>(yf3, yr3, g3, be3, g3, be3,
                                        (const float*)nullptr, y3o, L3, 8);
    combine_kernel<<<BATCH * L2, 256>>>(yf2, yr2, g2, be2, g2, be2,
                                        y3o, y2o, L2, 16);
    combine_kernel<<<BATCH * L1, 256>>>(yf1, yr1, g1, be1, g2, be2,
                                        y2o, y1o, L1, 32);

    // 8) gate with silu(z) + transpose to [b][c][p]
    gate_kernel<<<dim3(32, 8, BATCH), dim3(32, 8)>>>(y1o, xz, gated);

    // 9) out-projection straight into d_out: M=512,N=1024,K=256
    sgemm_kernel<<<dim3(8, 4, BATCH), 256>>>(out_w, gated, outp, out_b,
        512, 1024, 256, 256, 1024, 256LL * 1024, 512LL * 1024, 1024, 1);
}

// round 5
// speedup vs baseline: 1.5703x; 1.5703x over previous
#include <cuda_runtime.h>
#include <math.h>
#include <stddef.h>

// ---------------------------------------------------------------------------
// Problem constants (fixed by the dataset)
// ---------------------------------------------------------------------------
constexpr int BATCH  = 8;
constexpr int L1 = 1024, L2 = 256, L3 = 64;

// ---------------------------------------------------------------------------
// Scratch (single __device__ buffer; no allocations anywhere)
// ---------------------------------------------------------------------------
constexpr size_t SZ_XZ   = (size_t)BATCH * 512 * 1024;
constexpr size_t SZ_F1   = (size_t)BATCH * 256 * 1024;
constexpr size_t SZ_F2   = (size_t)BATCH * 256 * 256;
constexpr size_t SZ_F3   = (size_t)BATCH * 256 * 64;
constexpr size_t SZ_COL2 = (size_t)BATCH * 1024 * 256;
constexpr size_t SZ_COL3 = (size_t)BATCH * 1024 * 64;
constexpr size_t SZ_XD1  = (size_t)BATCH * 1024 * 40;
constexpr size_t SZ_XD2  = (size_t)BATCH * 256 * 40;
constexpr size_t SZ_XD3  = (size_t)BATCH * 64 * 40;
constexpr size_t SZ_Y1   = (size_t)BATCH * 1024 * 256;
constexpr size_t SZ_Y2   = (size_t)BATCH * 256 * 256;
constexpr size_t SZ_Y3   = (size_t)BATCH * 64 * 256;

constexpr size_t OFF_XZ    = 0;
constexpr size_t OFF_F1    = OFF_XZ   + SZ_XZ;
constexpr size_t OFF_F2    = OFF_F1   + SZ_F1;
constexpr size_t OFF_F3    = OFF_F2   + SZ_F2;
constexpr size_t OFF_COL2  = OFF_F3   + SZ_F3;
constexpr size_t OFF_COL3  = OFF_COL2 + SZ_COL2;
constexpr size_t OFF_XD1A  = OFF_COL3 + SZ_COL3;
constexpr size_t OFF_XD1B  = OFF_XD1A + SZ_XD1;
constexpr size_t OFF_XD2   = OFF_XD1B + SZ_XD1;
constexpr size_t OFF_XD3   = OFF_XD2  + SZ_XD2;
constexpr size_t OFF_YF1   = OFF_XD3  + SZ_XD3;
constexpr size_t OFF_YR1   = OFF_YF1  + SZ_Y1;
constexpr size_t OFF_YF2   = OFF_YR1  + SZ_Y1;
constexpr size_t OFF_YR2   = OFF_YF2  + SZ_Y2;
constexpr size_t OFF_YF3   = OFF_YR2  + SZ_Y2;
constexpr size_t OFF_YR3   = OFF_YF3  + SZ_Y3;
constexpr size_t OFF_Y3O   = OFF_YR3  + SZ_Y3;
constexpr size_t OFF_Y2O   = OFF_Y3O  + SZ_Y3;
constexpr size_t OFF_Y1O   = OFF_Y2O  + SZ_Y2;
constexpr size_t OFF_GATED = OFF_Y1O  + SZ_Y1;
constexpr size_t SCRATCH_TOTAL = OFF_GATED + SZ_F1;

__device__ float g_scratch[SCRATCH_TOTAL];

// ---------------------------------------------------------------------------
// 64x64x16 SGEMM, 128 threads, 8x4 microtile. High-occupancy tile used for
// EVERY GEMM so even small shapes fill all 148 SMs.
//   C[m,n] = sum_k A[m,k]*B[k,n] (+bias[m])
//   A row-major [M,K] (lda, shared across batch); B row-major [K,N] (ldb),
//   batched over blockIdx.z = batch*ksplit + ks.
//   C written at Cp[m*ldcm + n*ldcn].
//   Requires N % 64 == 0, (K/ksplit) % 16 == 0. M may be ragged (guarded).
//   ksplit>1 -> partial sums via atomicAdd (C must be pre-initialized).
// ---------------------------------------------------------------------------
#define SBM 64
#define SBN 64
#define SBK 16

__global__ __launch_bounds__(128)
void sgemm64_kernel(const float* __restrict__ A, const float* __restrict__ B,
                    float* __restrict__ C, const float* __restrict__ bias,
                    int M, int N, int K, int lda, int ldb,
                    long long strideB, long long strideC,
                    int ldcm, int ldcn, int ksplit)
{
    __shared__ float As[SBK][SBM];
    __shared__ float Bs[SBK][SBN];

    const int tid   = threadIdx.x;
    const int batch = blockIdx.z / ksplit;
    const int ks    = blockIdx.z % ksplit;
    const int kchunk = K / ksplit;
    const int kbeg   = ks * kchunk;
    const int m0 = blockIdx.y * SBM;
    const int n0 = blockIdx.x * SBN;

    const float* Bp = B + (size_t)batch * (size_t)strideB;
    float* Cp = C + (size_t)batch * (size_t)strideC;

    const int tx = tid & 15;       // N: 16 * 4
    const int ty = tid >> 4;       // M: 8 * 8

    float acc[8][4];
#pragma unroll
    for (int i = 0; i < 8; i++)
#pragma unroll
        for (int j = 0; j < 4; j++) acc[i][j] = 0.f;

    const int arow = tid >> 1;        // 0..63
    const int acol = (tid & 1) * 8;   // 0 or 8
    const int brow = tid >> 3;        // 0..15
    const int bcol = (tid & 7) * 8;   // 0..56

    for (int k0 = kbeg; k0 < kbeg + kchunk; k0 += SBK) {
        // A tile (64 x 16) -> As[k][m] transposed
        {
            const int m = m0 + arow;
            if (m < M) {
                const float* ap = A + (size_t)m * lda + k0 + acol;
                float4 a0 = *reinterpret_cast<const float4*>(ap);
                float4 a1 = *reinterpret_cast<const float4*>(ap + 4);
                As[acol + 0][arow] = a0.x; As[acol + 1][arow] = a0.y;
                As[acol + 2][arow] = a0.z; As[acol + 3][arow] = a0.w;
                As[acol + 4][arow] = a1.x; As[acol + 5][arow] = a1.y;
                As[acol + 6][arow] = a1.z; As[acol + 7][arow] = a1.w;
            } else {
#pragma unroll
                for (int i = 0; i < 8; i++) As[acol + i][arow] = 0.f;
            }
        }
        // B tile (16 x 64)
        {
            const float* bp = Bp + (size_t)(k0 + brow) * ldb + n0 + bcol;
            *reinterpret_cast<float4*>(&Bs[brow][bcol]) =
                *reinterpret_cast<const float4*>(bp);
            *reinterpret_cast<float4*>(&Bs[brow][bcol + 4]) =
                *reinterpret_cast<const float4*>(bp + 4);
        }
        __syncthreads();

#pragma unroll
        for (int kk = 0; kk < SBK; kk++) {
            const float4 a0 = *reinterpret_cast<const float4*>(&As[kk][ty * 8]);
            const float4 a1 = *reinterpret_cast<const float4*>(&As[kk][ty * 8 + 4]);
            const float4 b0 = *reinterpret_cast<const float4*>(&Bs[kk][tx * 4]);
            const float av[8] = {a0.x, a0.y, a0.z, a0.w, a1.x, a1.y, a1.z, a1.w};
            const float bv[4] = {b0.x, b0.y, b0.z, b0.w};
#pragma unroll
            for (int i = 0; i < 8; i++)
#pragma unroll
                for (int j = 0; j < 4; j++)
                    acc[i][j] += av[i] * bv[j];
        }
        __syncthreads();
    }

#pragma unroll
    for (int i = 0; i < 8; i++) {
        const int m = m0 + ty * 8 + i;
        if (m >= M) continue;
        if (ksplit == 1) {
            const float bv = bias ? bias[m] : 0.f;
#pragma unroll
            for (int j = 0; j < 4; j++) {
                const int n = n0 + tx * 4 + j;
                Cp[(size_t)m * ldcm + (size_t)n * ldcn] = acc[i][j] + bv;
            }
        } else {
#pragma unroll
            for (int j = 0; j < 4; j++) {
                const int n = n0 + tx * 4 + j;
                atomicAdd(&Cp[(size_t)m * ldcm + (size_t)n * ldcn], acc[i][j]);
            }
        }
    }
}

// ---------------------------------------------------------------------------
// bias init for split-K accumulation targets: C[b][m][n] = bias[m]
// ---------------------------------------------------------------------------
__global__ void biasinit_k(float* __restrict__ C, const float* __restrict__ bias,
                           int M, int N, int total)
{
    const int idx = blockIdx.x * blockDim.x + threadIdx.x;
    if (idx >= total) return;
    const int m = (idx / N) % M;
    C[idx] = bias[m];
}

// ---------------------------------------------------------------------------
// im2col for 2x2/stride-2 conv: src [B][C][Hs][Ws] -> dst [B][C*4][Ho*Wo]
// ---------------------------------------------------------------------------
__global__ void im2col_k(const float* __restrict__ src, float* __restrict__ dst,
                         int C, int Hs, int Ws)
{
    const int Ho = Hs >> 1, Wo = Ws >> 1;
    const int P = Ho * Wo;
    const int nTot = BATCH * C * 4 * P;
    const int idx = blockIdx.x * blockDim.x + threadIdx.x;
    if (idx >= nTot) return;
    const int n = idx % P;
    const int k = (idx / P) % (C * 4);
    const int b = idx / (P * C * 4);
    const int c = k >> 2;
    const int i = (k >> 1) & 1;
    const int j = k & 1;
    const int h = n / Wo;
    const int w = n % Wo;
    dst[idx] = src[(((size_t)b * C + c) * Hs + 2 * h + i) * Ws + 2 * w + j];
}

// ---------------------------------------------------------------------------
// Selective-scan kernel: 6 scans in one launch (blockIdx.y = scan id).
// One thread per (b,d). xd layout [b][L][40] (dts|Bs|Cs). x layout [b][d][L].
// dir=1 reads & writes at L-1-t => buffer holds flip(ssm(flip(x))) directly
// (valid because LayerNorm commutes with flip).
// ---------------------------------------------------------------------------
struct ScanCfg {
    const float* x;
    const float* xd;
    float* y;
    const float* dtw;
    const float* dtb;
    const float* Al;
    const float* Dv;
    int L;
    int dir;
};
struct ScanArgs { ScanCfg c[6]; };

__global__ __launch_bounds__(128)
void scan_kernel(ScanArgs args)
{
    const ScanCfg cfg = args.c[blockIdx.y];
    const int gid = blockIdx.x * 128 + threadIdx.x;   // 0..2047
    const int b = gid >> 8;
    const int d = gid & 255;
    const int L = cfg.L;
    const int dir = cfg.dir;

    float dtw_r[8];
#pragma unroll
    for (int i = 0; i < 8; i++) dtw_r[i] = cfg.dtw[d * 8 + i];
    const float dtb_r = cfg.dtb[d];
    const float Dv_r  = cfg.Dv[d];

    float A_r[16];
    bool pw = true;
#pragma unroll
    for (int n = 0; n < 16; n++) {
        A_r[n] = -expf(cfg.Al[d * 16 + n]);
        pw = pw && (fabsf(A_r[n] + (float)(n + 1)) <= 1e-4f * (float)(n + 1));
    }

    const float* xrow = cfg.x + ((size_t)b * 256 + d) * (size_t)L;
    const float* xdb  = cfg.xd + (size_t)b * L * 40;
    float* yb = cfg.y + (size_t)b * L * 256 + d;

    float h[16];
#pragma unroll
    for (int n = 0; n < 16; n++) h[n] = 0.f;

    if (pw) {
        // A[d][n] == -(n+1): one exp per step, powers via multiply tree.
        for (int t = 0; t < L; t++) {
            const int l = dir ? (L - 1 - t) : t;
            const float4* q = reinterpret_cast<const float4*>(xdb + (size_t)l * 40);
            const float4 d0 = q[0], d1 = q[1];
            const float4 B0 = q[2], B1 = q[3], B2 = q[4], B3 = q[5];
            const float4 C0 = q[6], C1 = q[7], C2 = q[8], C3 = q[9];
            float pre = dtb_r
                + d0.x * dtw_r[0] + d0.y * dtw_r[1] + d0.z * dtw_r[2] + d0.w * dtw_r[3]
                + d1.x * dtw_r[4] + d1.y * dtw_r[5] + d1.z * dtw_r[6] + d1.w * dtw_r[7];
            const float delta = (pre > 20.f) ? pre : log1pf(__expf(pre));
            const float xv = xrow[l];
            const float dx = delta * xv;
            const float p1 = __expf(-delta);
            const float p2 = p1 * p1, p3 = p2 * p1, p4 = p2 * p2;
            const float p5 = p4 * p1, p6 = p4 * p2, p7 = p4 * p3, p8 = p4 * p4;
            const float p9 = p8 * p1, p10 = p8 * p2, p11 = p8 * p3, p12 = p8 * p4;
            const float p13 = p8 * p5, p14 = p8 * p6, p15 = p8 * p7, p16 = p8 * p8;
            const float rr[16] = {p1,p2,p3,p4,p5,p6,p7,p8,p9,p10,p11,p12,p13,p14,p15,p16};
            const float Bv[16] = {B0.x,B0.y,B0.z,B0.w,B1.x,B1.y,B1.z,B1.w,
                                  B2.x,B2.y,B2.z,B2.w,B3.x,B3.y,B3.z,B3.w};
            const float Cv[16] = {C0.x,C0.y,C0.z,C0.w,C1.x,C1.y,C1.z,C1.w,
                                  C2.x,C2.y,C2.z,C2.w,C3.x,C3.y,C3.z,C3.w};
            float yacc = xv * Dv_r;
#pragma unroll
            for (int n = 0; n < 16; n++) {
                h[n] = h[n] * rr[n] + dx * Bv[n];
                yacc += h[n] * Cv[n];
            }
            yb[(size_t)l * 256] = yacc;
        }
    } else {
        // General path (data-independent correctness guarantee).
        for (int t = 0; t < L; t++) {
            const int l = dir ? (L - 1 - t) : t;
            const float4* q = reinterpret_cast<const float4*>(xdb + (size_t)l * 40);
            const float4 d0 = q[0], d1 = q[1];
            const float4 B0 = q[2], B1 = q[3], B2 = q[4], B3 = q[5];
            const float4 C0 = q[6], C1 = q[7], C2 = q[8], C3 = q[9];
            float pre = dtb_r
                + d0.x * dtw_r[0] + d0.y * dtw_r[1] + d0.z * dtw_r[2] + d0.w * dtw_r[3]
                + d1.x * dtw_r[4] + d1.y * dtw_r[5] + d1.z * dtw_r[6] + d1.w * dtw_r[7];
            const float delta = (pre > 20.f) ? pre : log1pf(__expf(pre));
            const float xv = xrow[l];
            const float dx = delta * xv;
            const float Bv[16] = {B0.x,B0.y,B0.z,B0.w,B1.x,B1.y,B1.z,B1.w,
                                  B2.x,B2.y,B2.z,B2.w,B3.x,B3.y,B3.z,B3.w};
            const float Cv[16] = {C0.x,C0.y,C0.z,C0.w,C1.x,C1.y,C1.z,C1.w,
                                  C2.x,C2.y,C2.z,C2.w,C3.x,C3.y,C3.z,C3.w};
            float yacc = xv * Dv_r;
#pragma unroll
            for (int n = 0; n < 16; n++) {
                h[n] = h[n] * __expf(delta * A_r[n]) + dx * Bv[n];
                yacc += h[n] * Cv[n];
            }
            yb[(size_t)l * 256] = yacc;
        }
    }
}

// ---------------------------------------------------------------------------
// Combine: out[b,l,:] = LN(yf)*gf+bef + LN(yr)*gr+ber + up2(src)
// ---------------------------------------------------------------------------
__device__ __forceinline__ float4 warpReduce4(float4 v)
{
#pragma unroll
    for (int o = 16; o > 0; o >>= 1) {
        v.x += __shfl_xor_sync(0xffffffffu, v.x, o);
        v.y += __shfl_xor_sync(0xffffffffu, v.y, o);
        v.z += __shfl_xor_sync(0xffffffffu, v.z, o);
        v.w += __shfl_xor_sync(0xffffffffu, v.w, o);
    }
    return v;
}

__global__ __launch_bounds__(256)
void combine_kernel(const float* __restrict__ yf, const float* __restrict__ yr,
                    const float* __restrict__ gf, const float* __restrict__ bef,
                    const float* __restrict__ gr, const float* __restrict__ ber,
                    const float* __restrict__ up, float* __restrict__ out,
                    int L, int wgrid)
{
    __shared__ float4 red[8];
    const int bl = blockIdx.x;              // b*L + l
    const int d  = threadIdx.x;             // 0..255
    const size_t base = (size_t)bl * 256;

    const float vf = yf[base + d];
    const float vr = yr[base + d];

    float4 s = warpReduce4(make_float4(vf, vf * vf, vr, vr * vr));
    const int warp = threadIdx.x >> 5;
    const int lane = threadIdx.x & 31;
    if (lane == 0) red[warp] = s;
    __syncthreads();
    if (warp == 0) {
        float4 t = (lane < 8) ? red[lane] : make_float4(0.f, 0.f, 0.f, 0.f);
#pragma unroll
        for (int o = 4; o > 0; o >>= 1) {
            t.x += __shfl_xor_sync(0xffffffffu, t.x, o);
            t.y += __shfl_xor_sync(0xffffffffu, t.y, o);
            t.z += __shfl_xor_sync(0xffffffffu, t.z, o);
            t.w += __shfl_xor_sync(0xffffffffu, t.w, o);
        }
        if (lane == 0) red[0] = t;
    }
    __syncthreads();
    const float4 tot = red[0];

    const float inv = 1.f / 256.f;
    const float muf = tot.x * inv;
    const float varf = tot.y * inv - muf * muf;
    const float mur = tot.z * inv;
    const float varr = tot.w * inv - mur * mur;

    const float of = (vf - muf) * rsqrtf(varf + 1e-5f) * gf[d] + bef[d];
    const float orr = (vr - mur) * rsqrtf(varr + 1e-5f) * gr[d] + ber[d];

    float u = 0.f;
    if (up) {
        const int b = bl / L, l = bl % L;
        const int hh = l / wgrid, ww = l % wgrid;
        const int lsrc = (hh >> 1) * (wgrid >> 1) + (ww >> 1);
        u = up[((size_t)b * (L >> 2) + lsrc) * 256 + d];
    }
    out[base + d] = of + orr + u;
}

// ---------------------------------------------------------------------------
// Gate: gated[b][c][p] = y1o[b][p][c] * silu(xz[b][256+c][p])
// ---------------------------------------------------------------------------
__global__ __launch_bounds__(256)
void gate_kernel(const float* __restrict__ y1o, const float* __restrict__ xz,
                 float* __restrict__ gated)
{
    __shared__ float tile[32][33];
    const int b = blockIdx.z;
    const int p0 = blockIdx.x * 32;
    const int c0 = blockIdx.y * 32;
    const int tx = threadIdx.x;   // 0..31
    const int ty = threadIdx.y;   // 0..7

#pragma unroll
    for (int k = 0; k < 4; k++) {
        const int p = p0 + ty + k * 8;
        tile[ty + k * 8][tx] = y1o[((size_t)b * 1024 + p) * 256 + c0 + tx];
    }
    __syncthreads();
#pragma unroll
    for (int k = 0; k < 4; k++) {
        const int c = c0 + ty + k * 8;
        const int p = p0 + tx;
        const float z = xz[((size_t)b * 512 + 256 + c) * 1024 + p];
        const float sz = z / (1.f + __expf(-z));
        gated[((size_t)b * 256 + c) * 1024 + p] = tile[tx][ty + k * 8] * sz;
    }
}

// ---------------------------------------------------------------------------
// Launcher
// ---------------------------------------------------------------------------
extern "C" void kernel_launch(void* const* d_in, const int* in_sizes, int n_in,
                              void* d_out, int out_size)
{
    const float* input_f = (const float*)d_in[0];
    const float* in_w    = (const float*)d_in[1];
    const float* in_b    = (const float*)d_in[2];
    const float* c1_w    = (const float*)d_in[3];
    const float* c1_b    = (const float*)d_in[4];
    const float* c2_w    = (const float*)d_in[5];
    const float* c2_b    = (const float*)d_in[6];
    const float* c3_w    = (const float*)d_in[7];
    const float* c3_b    = (const float*)d_in[8];
    const float* out_w   = (const float*)d_in[9];
    const float* out_b   = (const float*)d_in[10];
    const float* xw1  = (const float*)d_in[11];
    const float* dtw1 = (const float*)d_in[12];
    const float* dtb1 = (const float*)d_in[13];
    const float* Al1  = (const float*)d_in[14];
    const float* Dv1  = (const float*)d_in[15];
    const float* g1   = (const float*)d_in[16];
    const float* be1  = (const float*)d_in[17];
    const float* xw2  = (const float*)d_in[18];
    const float* dtw2 = (const float*)d_in[19];
    const float* dtb2 = (const float*)d_in[20];
    const float* Al2  = (const float*)d_in[21];
    const float* Dv2  = (const float*)d_in[22];
    const float* g2   = (const float*)d_in[23];
    const float* be2  = (const float*)d_in[24];
    const float* xw3  = (const float*)d_in[25];
    const float* dtw3 = (const float*)d_in[26];
    const float* dtb3 = (const float*)d_in[27];
    const float* Al3  = (const float*)d_in[28];
    const float* Dv3  = (const float*)d_in[29];
    const float* g3   = (const float*)d_in[30];
    const float* be3  = (const float*)d_in[31];
    (void)in_sizes; (void)n_in; (void)out_size;

    float* scratch = nullptr;
    cudaGetSymbolAddress((void**)&scratch, g_scratch);

    float* xz   = scratch + OFF_XZ;
    float* f1   = scratch + OFF_F1;
    float* f2   = scratch + OFF_F2;
    float* f3   = scratch + OFF_F3;
    float* col2 = scratch + OFF_COL2;
    float* col3 = scratch + OFF_COL3;
    float* xd1a = scratch + OFF_XD1A;
    float* xd1b = scratch + OFF_XD1B;
    float* xd2  = scratch + OFF_XD2;
    float* xd3  = scratch + OFF_XD3;
    float* yf1  = scratch + OFF_YF1;
    float* yr1  = scratch + OFF_YR1;
    float* yf2  = scratch + OFF_YF2;
    float* yr2  = scratch + OFF_YR2;
    float* yf3  = scratch + OFF_YF3;
    float* yr3  = scratch + OFF_YR3;
    float* y3o  = scratch + OFF_Y3O;
    float* y2o  = scratch + OFF_Y2O;
    float* y1o  = scratch + OFF_Y1O;
    float* gated = scratch + OFF_GATED;
    float* outp = (float*)d_out;

    // 1) in-projection: xz[b][o][p], M=512,N=1024,K=512 -> 1024 blocks
    sgemm64_kernel<<<dim3(16, 8, BATCH), 128>>>(in_w, input_f, xz, in_b,
        512, 1024, 512, 512, 1024, 512LL * 1024, 512LL * 1024, 1024, 1, 1);

    // 2) c1: f1 = conv1x1(x): M=256,N=1024,K=256 -> 512 blocks
    sgemm64_kernel<<<dim3(16, 4, BATCH), 128>>>(c1_w, xz, f1, c1_b,
        256, 1024, 256, 256, 1024, 512LL * 1024, 256LL * 1024, 1024, 1, 1);

    // 3) f2 = conv2s2(f1): im2col + GEMM (K = 1024) -> 128 blocks
    im2col_k<<<(BATCH * 256 * 4 * 256 + 255) / 256, 256>>>(f1, col2, 256, 32, 32);
    sgemm64_kernel<<<dim3(4, 4, BATCH), 128>>>(c2_w, col2, f2, c2_b,
        256, 256, 1024, 1024, 256, 1024LL * 256, 256LL * 256, 256, 1, 1);

    // 4) f3 = conv2s2(f2): split-K 4 (atomic) -> 128 blocks
    im2col_k<<<(BATCH * 256 * 4 * 64 + 255) / 256, 256>>>(f2, col3, 256, 16, 16);
    biasinit_k<<<(BATCH * 256 * 64 + 255) / 256, 256>>>(f3, c3_b, 256, 64,
                                                        BATCH * 256 * 64);
    sgemm64_kernel<<<dim3(1, 4, BATCH * 4), 128>>>(c3_w, col3, f3, nullptr,
        256, 64, 1024, 1024, 64, 1024LL * 64, 256LL * 64, 64, 1, 4);

    // 5) xd projections -> [b][L][40]  (C transposed: ldcm=1, ldcn=40)
    sgemm64_kernel<<<dim3(16, 1, BATCH), 128>>>(xw1, f1, xd1a, nullptr,
        40, 1024, 256, 256, 1024, 256LL * 1024, 1024LL * 40, 1, 40, 1);
    sgemm64_kernel<<<dim3(16, 1, BATCH), 128>>>(xw2, f1, xd1b, nullptr,
        40, 1024, 256, 256, 1024, 256LL * 1024, 1024LL * 40, 1, 40, 1);
    sgemm64_kernel<<<dim3(4, 1, BATCH), 128>>>(xw2, f2, xd2, nullptr,
        40, 256, 256, 256, 256, 256LL * 256, 256LL * 40, 1, 40, 1);
    sgemm64_kernel<<<dim3(1, 1, BATCH), 128>>>(xw3, f3, xd3, nullptr,
        40, 64, 256, 256, 64, 256LL * 64, 64LL * 40, 1, 40, 1);

    // 6) all six selective scans in one launch
    ScanArgs sa;
    sa.c[0] = {f1, xd1a, yf1, dtw1, dtb1, Al1, Dv1, L1, 0};  // L1 fwd (params1)
    sa.c[1] = {f1, xd1b, yr1, dtw2, dtb2, Al2, Dv2, L1, 1};  // L1 rev (params2! — ref quirk)
    sa.c[2] = {f2, xd2,  yf2, dtw2, dtb2, Al2, Dv2, L2, 0};
    sa.c[3] = {f2, xd2,  yr2, dtw2, dtb2, Al2, Dv2, L2, 1};
    sa.c[4] = {f3, xd3,  yf3, dtw3, dtb3, Al3, Dv3, L3, 0};
    sa.c[5] = {f3, xd3,  yr3, dtw3, dtb3, Al3, Dv3, L3, 1};
    scan_kernel<<<dim3(16, 6), 128>>>(sa);

    // 7) combine (LayerNorm per direction + sum + upsample-add), bottom-up
    combine_kernel<<<BATCH * L3, 256>>>(yf3, yr3, g3, be3, g3, be3,
                                        (const float*)nullptr, y3o, L3, 8);
    combine_kernel<<<BATCH * L2, 256>>>(yf2, yr2, g2, be2, g2, be2,
                                        y3o, y2o, L2, 16);
    combine_kernel<<<BATCH * L1, 256>>>(yf1, yr1, g1, be1, g2, be2,
                                        y2o, y1o, L1, 32);

    // 8) gate with silu(z) + transpose to [b][c][p]
    gate_kernel<<<dim3(32, 8, BATCH), dim3(32, 8)>>>(y1o, xz, gated);

    // 9) out-projection straight into d_out: M=512,N=1024,K=256 -> 1024 blocks
    sgemm64_kernel<<<dim3(16, 8, BATCH), 128>>>(out_w, gated, outp, out_b,
        512, 1024, 256, 256, 1024, 256LL * 1024, 512LL * 1024, 1024, 1, 1);
}

// round 7
// speedup vs baseline: 1.6341x; 1.0406x over previous
#include <cuda_runtime.h>
#include <math.h>
#include <stddef.h>

// ---------------------------------------------------------------------------
// Problem constants (fixed by the dataset)
// ---------------------------------------------------------------------------
constexpr int BATCH  = 8;
constexpr int L1 = 1024, L2 = 256, L3 = 64;

// ---------------------------------------------------------------------------
// Scratch (single __device__ buffer; no allocations anywhere)
// ---------------------------------------------------------------------------
constexpr size_t SZ_XZ    = (size_t)BATCH * 512 * 1024;
constexpr size_t SZ_F1    = (size_t)BATCH * 256 * 1024;
constexpr size_t SZ_F2    = (size_t)BATCH * 256 * 256;
constexpr size_t SZ_F3    = (size_t)BATCH * 256 * 64;
constexpr size_t SZ_COL2  = (size_t)BATCH * 1024 * 256;
constexpr size_t SZ_COL3  = (size_t)BATCH * 1024 * 64;
constexpr size_t SZ_XD1AB = (size_t)BATCH * 1024 * 80;   // merged xw1|xw2 proj
constexpr size_t SZ_XD2   = (size_t)BATCH * 256 * 40;
constexpr size_t SZ_XD3   = (size_t)BATCH * 64 * 40;
constexpr size_t SZ_WCAT  = (size_t)80 * 256;
constexpr size_t SZ_Y1    = (size_t)BATCH * 1024 * 256;
constexpr size_t SZ_Y2    = (size_t)BATCH * 256 * 256;
constexpr size_t SZ_Y3    = (size_t)BATCH * 64 * 256;

constexpr size_t OFF_XZ    = 0;
constexpr size_t OFF_F1    = OFF_XZ    + SZ_XZ;
constexpr size_t OFF_F2    = OFF_F1    + SZ_F1;
constexpr size_t OFF_F3    = OFF_F2    + SZ_F2;
constexpr size_t OFF_COL2  = OFF_F3    + SZ_F3;
constexpr size_t OFF_COL3  = OFF_COL2  + SZ_COL2;
constexpr size_t OFF_XD1AB = OFF_COL3  + SZ_COL3;
constexpr size_t OFF_XD2   = OFF_XD1AB + SZ_XD1AB;
constexpr size_t OFF_XD3   = OFF_XD2   + SZ_XD2;
constexpr size_t OFF_WCAT  = OFF_XD3   + SZ_XD3;
constexpr size_t OFF_YF1   = OFF_WCAT  + SZ_WCAT;
constexpr size_t OFF_YR1   = OFF_YF1   + SZ_Y1;
constexpr size_t OFF_YF2   = OFF_YR1   + SZ_Y1;
constexpr size_t OFF_YR2   = OFF_YF2   + SZ_Y2;
constexpr size_t OFF_YF3   = OFF_YR2   + SZ_Y2;
constexpr size_t OFF_YR3   = OFF_YF3   + SZ_Y3;
constexpr size_t OFF_Y3O   = OFF_YR3   + SZ_Y3;
constexpr size_t OFF_Y2O   = OFF_Y3O   + SZ_Y3;
constexpr size_t OFF_Y1O   = OFF_Y2O   + SZ_Y2;
constexpr size_t OFF_GATED = OFF_Y1O   + SZ_Y1;
constexpr size_t SCRATCH_TOTAL = OFF_GATED + SZ_F1;

__device__ float g_scratch[SCRATCH_TOTAL];

// ---------------------------------------------------------------------------
// 64x64x16 SGEMM, 128 threads, 8x4 microtile, double-buffered SMEM with
// global->register prefetch (one __syncthreads per K-tile).
//   C[m,n] = sum_k A[m,k]*B[k,n] (+bias[m])
//   A row-major [M,K] (lda, shared across batch); B row-major [K,N] (ldb),
//   batched over blockIdx.z = batch*ksplit + ks.
//   C written at Cp[m*ldcm + n*ldcn].
//   Requires N % 64 == 0, (K/ksplit) % 16 == 0, K/ksplit >= 32.
//   ksplit>1 -> partial sums via atomicAdd (C must be pre-initialized).
// ---------------------------------------------------------------------------
#define SBM 64
#define SBN 64
#define SBK 16

__global__ __launch_bounds__(128)
void sgemm64_kernel(const float* __restrict__ A, const float* __restrict__ B,
                    float* __restrict__ C, const float* __restrict__ bias,
                    int M, int N, int K, int lda, int ldb,
                    long long strideB, long long strideC,
                    int ldcm, int ldcn, int ksplit)
{
    __shared__ float As[2][SBK][SBM];
    __shared__ float Bs[2][SBK][SBN];

    const int tid   = threadIdx.x;
    const int batch = blockIdx.z / ksplit;
    const int ks    = blockIdx.z % ksplit;
    const int kchunk = K / ksplit;
    const int kbeg   = ks * kchunk;
    const int kend   = kbeg + kchunk;
    const int m0 = blockIdx.y * SBM;
    const int n0 = blockIdx.x * SBN;

    const float* Bp = B + (size_t)batch * (size_t)strideB;
    float* Cp = C + (size_t)batch * (size_t)strideC;

    const int tx = tid & 15;       // N: 16 * 4
    const int ty = tid >> 4;       // M: 8 * 8

    const int arow = tid >> 1;        // 0..63
    const int acol = (tid & 1) * 8;   // 0 or 8
    const int brow = tid >> 3;        // 0..15
    const int bcol = (tid & 7) * 8;   // 0..56

    const bool aval = (m0 + arow) < M;
    const float* aptr = A + (size_t)(m0 + arow) * lda + acol;
    const float* bptr = Bp + (size_t)brow * ldb + n0 + bcol;

    float acc[8][4];
#pragma unroll
    for (int i = 0; i < 8; i++)
#pragma unroll
        for (int j = 0; j < 4; j++) acc[i][j] = 0.f;

    float apf[8], bpf[8];

    // prefetch tile 0
    {
        if (aval) {
            float4 a0 = *reinterpret_cast<const float4*>(aptr + kbeg);
            float4 a1 = *reinterpret_cast<const float4*>(aptr + kbeg + 4);
            apf[0]=a0.x; apf[1]=a0.y; apf[2]=a0.z; apf[3]=a0.w;
            apf[4]=a1.x; apf[5]=a1.y; apf[6]=a1.z; apf[7]=a1.w;
        } else {
#pragma unroll
            for (int i = 0; i < 8; i++) apf[i] = 0.f;
        }
        const float* bp = bptr + (size_t)kbeg * ldb;
        float4 b0 = *reinterpret_cast<const float4*>(bp);
        float4 b1 = *reinterpret_cast<const float4*>(bp + 4);
        bpf[0]=b0.x; bpf[1]=b0.y; bpf[2]=b0.z; bpf[3]=b0.w;
        bpf[4]=b1.x; bpf[5]=b1.y; bpf[6]=b1.z; bpf[7]=b1.w;
    }
    // store tile 0
#pragma unroll
    for (int i = 0; i < 8; i++) As[0][acol + i][arow] = apf[i];
    *reinterpret_cast<float4*>(&Bs[0][brow][bcol])     = make_float4(bpf[0],bpf[1],bpf[2],bpf[3]);
    *reinterpret_cast<float4*>(&Bs[0][brow][bcol + 4]) = make_float4(bpf[4],bpf[5],bpf[6],bpf[7]);
    __syncthreads();

    int cur = 0;
    for (int k0 = kbeg + SBK; k0 < kend; k0 += SBK) {
        // prefetch next tile into registers
        if (aval) {
            float4 a0 = *reinterpret_cast<const float4*>(aptr + k0);
            float4 a1 = *reinterpret_cast<const float4*>(aptr + k0 + 4);
            apf[0]=a0.x; apf[1]=a0.y; apf[2]=a0.z; apf[3]=a0.w;
            apf[4]=a1.x; apf[5]=a1.y; apf[6]=a1.z; apf[7]=a1.w;
        }
        {
            const float* bp = bptr + (size_t)k0 * ldb;
            float4 b0 = *reinterpret_cast<const float4*>(bp);
            float4 b1 = *reinterpret_cast<const float4*>(bp + 4);
            bpf[0]=b0.x; bpf[1]=b0.y; bpf[2]=b0.z; bpf[3]=b0.w;
            bpf[4]=b1.x; bpf[5]=b1.y; bpf[6]=b1.z; bpf[7]=b1.w;
        }

        // FMA over current buffer
#pragma unroll
        for (int kk = 0; kk < SBK; kk++) {
            const float4 a0 = *reinterpret_cast<const float4*>(&As[cur][kk][ty * 8]);
            const float4 a1 = *reinterpret_cast<const float4*>(&As[cur][kk][ty * 8 + 4]);
            const float4 b0 = *reinterpret_cast<const float4*>(&Bs[cur][kk][tx * 4]);
            const float av[8] = {a0.x, a0.y, a0.z, a0.w, a1.x, a1.y, a1.z, a1.w};
            const float bv[4] = {b0.x, b0.y, b0.z, b0.w};
#pragma unroll
            for (int i = 0; i < 8; i++)
#pragma unroll
                for (int j = 0; j < 4; j++)
                    acc[i][j] += av[i] * bv[j];
        }

        // store prefetched tile into the other buffer (safe: last read of that
        // buffer was followed by the previous iteration's __syncthreads)
        const int nxt = cur ^ 1;
#pragma unroll
        for (int i = 0; i < 8; i++) As[nxt][acol + i][arow] = apf[i];
        *reinterpret_cast<float4*>(&Bs[nxt][brow][bcol])     = make_float4(bpf[0],bpf[1],bpf[2],bpf[3]);
        *reinterpret_cast<float4*>(&Bs[nxt][brow][bcol + 4]) = make_float4(bpf[4],bpf[5],bpf[6],bpf[7]);
        __syncthreads();
        cur = nxt;
    }

    // final tile
#pragma unroll
    for (int kk = 0; kk < SBK; kk++) {
        const float4 a0 = *reinterpret_cast<const float4*>(&As[cur][kk][ty * 8]);
        const float4 a1 = *reinterpret_cast<const float4*>(&As[cur][kk][ty * 8 + 4]);
        const float4 b0 = *reinterpret_cast<const float4*>(&Bs[cur][kk][tx * 4]);
        const float av[8] = {a0.x, a0.y, a0.z, a0.w, a1.x, a1.y, a1.z, a1.w};
        const float bv[4] = {b0.x, b0.y, b0.z, b0.w};
#pragma unroll
        for (int i = 0; i < 8; i++)
#pragma unroll
            for (int j = 0; j < 4; j++)
                acc[i][j] += av[i] * bv[j];
    }

#pragma unroll
    for (int i = 0; i < 8; i++) {
        const int m = m0 + ty * 8 + i;
        if (m >= M) continue;
        if (ksplit == 1) {
            const float bv = bias ? bias[m] : 0.f;
#pragma unroll
            for (int j = 0; j < 4; j++) {
                const int n = n0 + tx * 4 + j;
                Cp[(size_t)m * ldcm + (size_t)n * ldcn] = acc[i][j] + bv;
            }
        } else {
#pragma unroll
            for (int j = 0; j < 4; j++) {
                const int n = n0 + tx * 4 + j;
                atomicAdd(&Cp[(size_t)m * ldcm + (size_t)n * ldcn], acc[i][j]);
            }
        }
    }
}

// ---------------------------------------------------------------------------
// init for split-K targets: C[b][m][n] = bias ? bias[m] : 0
// ---------------------------------------------------------------------------
__global__ void biasinit_k(float* __restrict__ C, const float* __restrict__ bias,
                           int M, int N, int total)
{
    const int idx = blockIdx.x * blockDim.x + threadIdx.x;
    if (idx >= total) return;
    const int m = (idx / N) % M;
    C[idx] = bias ? bias[m] : 0.f;
}

// concat xw1 (40x256) and xw2 (40x256) -> wcat (80x256)
__global__ void wcat_k(const float* __restrict__ w1, const float* __restrict__ w2,
                       float* __restrict__ dst)
{
    const int idx = blockIdx.x * blockDim.x + threadIdx.x;
    if (idx >= 80 * 256) return;
    dst[idx] = (idx < 40 * 256) ? w1[idx] : w2[idx - 40 * 256];
}

// ---------------------------------------------------------------------------
// im2col for 2x2/stride-2 conv: src [B][C][Hs][Ws] -> dst [B][C*4][Ho*Wo]
// ---------------------------------------------------------------------------
__global__ void im2col_k(const float* __restrict__ src, float* __restrict__ dst,
                         int C, int Hs, int Ws)
{
    const int Ho = Hs >> 1, Wo = Ws >> 1;
    const int P = Ho * Wo;
    const int nTot = BATCH * C * 4 * P;
    const int idx = blockIdx.x * blockDim.x + threadIdx.x;
    if (idx >= nTot) return;
    const int n = idx % P;
    const int k = (idx / P) % (C * 4);
    const int b = idx / (P * C * 4);
    const int c = k >> 2;
    const int i = (k >> 1) & 1;
    const int j = k & 1;
    const int h = n / Wo;
    const int w = n % Wo;
    dst[idx] = src[(((size_t)b * C + c) * Hs + 2 * h + i) * Ws + 2 * w + j];
}

// ---------------------------------------------------------------------------
// Selective-scan kernel: 6 scans in one launch (blockIdx.y = scan id).
// One thread per (b,d). xd layout [b][L][pitch] (dts|Bs|Cs at given base).
// x layout [b][d][L]. dir=1 reads & writes at L-1-t => buffer holds
// flip(ssm(flip(x))) directly (LayerNorm commutes with flip).
// ---------------------------------------------------------------------------
struct ScanCfg {
    const float* x;
    const float* xd;
    float* y;
    const float* dtw;
    const float* dtb;
    const float* Al;
    const float* Dv;
    int L;
    int dir;
    int pitch;
};
struct ScanArgs { ScanCfg c[6]; };

__global__ __launch_bounds__(128)
void scan_kernel(ScanArgs args)
{
    const ScanCfg cfg = args.c[blockIdx.y];
    const int gid = blockIdx.x * 128 + threadIdx.x;   // 0..2047
    const int b = gid >> 8;
    const int d = gid & 255;
    const int L = cfg.L;
    const int dir = cfg.dir;
    const int pitch = cfg.pitch;

    float dtw_r[8];
#pragma unroll
    for (int i = 0; i < 8; i++) dtw_r[i] = cfg.dtw[d * 8 + i];
    const float dtb_r = cfg.dtb[d];
    const float Dv_r  = cfg.Dv[d];

    float A_r[16];
    bool pw = true;
#pragma unroll
    for (int n = 0; n < 16; n++) {
        A_r[n] = -expf(cfg.Al[d * 16 + n]);
        pw = pw && (fabsf(A_r[n] + (float)(n + 1)) <= 1e-4f * (float)(n + 1));
    }

    const float* xrow = cfg.x + ((size_t)b * 256 + d) * (size_t)L;
    const float* xdb  = cfg.xd + (size_t)b * L * pitch;
    float* yb = cfg.y + (size_t)b * L * 256 + d;

    float h[16];
#pragma unroll
    for (int n = 0; n < 16; n++) h[n] = 0.f;

    if (pw) {
        // A[d][n] == -(n+1): one exp per step, powers via multiply tree.
        for (int t = 0; t < L; t++) {
            const int l = dir ? (L - 1 - t) : t;
            const float4* q = reinterpret_cast<const float4*>(xdb + (size_t)l * pitch);
            const float4 d0 = q[0], d1 = q[1];
            const float4 B0 = q[2], B1 = q[3], B2 = q[4], B3 = q[5];
            const float4 C0 = q[6], C1 = q[7], C2 = q[8], C3 = q[9];
            float pre = dtb_r
                + d0.x * dtw_r[0] + d0.y * dtw_r[1] + d0.z * dtw_r[2] + d0.w * dtw_r[3]
                + d1.x * dtw_r[4] + d1.y * dtw_r[5] + d1.z * dtw_r[6] + d1.w * dtw_r[7];
            const float delta = (pre > 20.f) ? pre : log1pf(__expf(pre));
            const float xv = xrow[l];
            const float dx = delta * xv;
            const float p1 = __expf(-delta);
            const float p2 = p1 * p1, p3 = p2 * p1, p4 = p2 * p2;
            const float p5 = p4 * p1, p6 = p4 * p2, p7 = p4 * p3, p8 = p4 * p4;
            const float p9 = p8 * p1, p10 = p8 * p2, p11 = p8 * p3, p12 = p8 * p4;
            const float p13 = p8 * p5, p14 = p8 * p6, p15 = p8 * p7, p16 = p8 * p8;
            const float rr[16] = {p1,p2,p3,p4,p5,p6,p7,p8,p9,p10,p11,p12,p13,p14,p15,p16};
            const float Bv[16] = {B0.x,B0.y,B0.z,B0.w,B1.x,B1.y,B1.z,B1.w,
                                  B2.x,B2.y,B2.z,B2.w,B3.x,B3.y,B3.z,B3.w};
            const float Cv[16] = {C0.x,C0.y,C0.z,C0.w,C1.x,C1.y,C1.z,C1.w,
                                  C2.x,C2.y,C2.z,C2.w,C3.x,C3.y,C3.z,C3.w};
            float yacc = xv * Dv_r;
#pragma unroll
            for (int n = 0; n < 16; n++) {
                h[n] = h[n] * rr[n] + dx * Bv[n];
                yacc += h[n] * Cv[n];
            }
            yb[(size_t)l * 256] = yacc;
        }
    } else {
        // General path (data-independent correctness guarantee).
        for (int t = 0; t < L; t++) {
            const int l = dir ? (L - 1 - t) : t;
            const float4* q = reinterpret_cast<const float4*>(xdb + (size_t)l * pitch);
            const float4 d0 = q[0], d1 = q[1];
            const float4 B0 = q[2], B1 = q[3], B2 = q[4], B3 = q[5];
            const float4 C0 = q[6], C1 = q[7], C2 = q[8], C3 = q[9];
            float pre = dtb_r
                + d0.x * dtw_r[0] + d0.y * dtw_r[1] + d0.z * dtw_r[2] + d0.w * dtw_r[3]
                + d1.x * dtw_r[4] + d1.y * dtw_r[5] + d1.z * dtw_r[6] + d1.w * dtw_r[7];
            const float delta = (pre > 20.f) ? pre : log1pf(__expf(pre));
            const float xv = xrow[l];
            const float dx = delta * xv;
            const float Bv[16] = {B0.x,B0.y,B0.z,B0.w,B1.x,B1.y,B1.z,B1.w,
                                  B2.x,B2.y,B2.z,B2.w,B3.x,B3.y,B3.z,B3.w};
            const float Cv[16] = {C0.x,C0.y,C0.z,C0.w,C1.x,C1.y,C1.z,C1.w,
                                  C2.x,C2.y,C2.z,C2.w,C3.x,C3.y,C3.z,C3.w};
            float yacc = xv * Dv_r;
#pragma unroll
            for (int n = 0; n < 16; n++) {
                h[n] = h[n] * __expf(delta * A_r[n]) + dx * Bv[n];
                yacc += h[n] * Cv[n];
            }
            yb[(size_t)l * 256] = yacc;
        }
    }
}

// ---------------------------------------------------------------------------
// Combine: out[b,l,:] = LN(yf)*gf+bef + LN(yr)*gr+ber + up2(src)
// ---------------------------------------------------------------------------
__device__ __forceinline__ float4 warpReduce4(float4 v)
{
#pragma unroll
    for (int o = 16; o > 0; o >>= 1) {
        v.x += __shfl_xor_sync(0xffffffffu, v.x, o);
        v.y += __shfl_xor_sync(0xffffffffu, v.y, o);
        v.z += __shfl_xor_sync(0xffffffffu, v.z, o);
        v.w += __shfl_xor_sync(0xffffffffu, v.w, o);
    }
    return v;
}

__global__ __launch_bounds__(256)
void combine_kernel(const float* __restrict__ yf, const float* __restrict__ yr,
                    const float* __restrict__ gf, const float* __restrict__ bef,
                    const float* __restrict__ gr, const float* __restrict__ ber,
                    const float* __restrict__ up, float* __restrict__ out,
                    int L, int wgrid)
{
    __shared__ float4 red[8];
    const int bl = blockIdx.x;              // b*L + l
    const int d  = threadIdx.x;             // 0..255
    const size_t base = (size_t)bl * 256;

    const float vf = yf[base + d];
    const float vr = yr[base + d];

    float4 s = warpReduce4(make_float4(vf, vf * vf, vr, vr * vr));
    const int warp = threadIdx.x >> 5;
    const int lane = threadIdx.x & 31;
    if (lane == 0) red[warp] = s;
    __syncthreads();
    if (warp == 0) {
        float4 t = (lane < 8) ? red[lane] : make_float4(0.f, 0.f, 0.f, 0.f);
#pragma unroll
        for (int o = 4; o > 0; o >>= 1) {
            t.x += __shfl_xor_sync(0xffffffffu, t.x, o);
            t.y += __shfl_xor_sync(0xffffffffu, t.y, o);
            t.z += __shfl_xor_sync(0xffffffffu, t.z, o);
            t.w += __shfl_xor_sync(0xffffffffu, t.w, o);
        }
        if (lane == 0) red[0] = t;
    }
    __syncthreads();
    const float4 tot = red[0];

    const float inv = 1.f / 256.f;
    const float muf = tot.x * inv;
    const float varf = tot.y * inv - muf * muf;
    const float mur = tot.z * inv;
    const float varr = tot.w * inv - mur * mur;

    const float of = (vf - muf) * rsqrtf(varf + 1e-5f) * gf[d] + bef[d];
    const float orr = (vr - mur) * rsqrtf(varr + 1e-5f) * gr[d] + ber[d];

    float u = 0.f;
    if (up) {
        const int b = bl / L, l = bl % L;
        const int hh = l / wgrid, ww = l % wgrid;
        const int lsrc = (hh >> 1) * (wgrid >> 1) + (ww >> 1);
        u = up[((size_t)b * (L >> 2) + lsrc) * 256 + d];
    }
    out[base + d] = of + orr + u;
}

// ---------------------------------------------------------------------------
// Gate: gated[b][c][p] = y1o[b][p][c] * silu(xz[b][256+c][p])
// ---------------------------------------------------------------------------
__global__ __launch_bounds__(256)
void gate_kernel(const float* __restrict__ y1o, const float* __restrict__ xz,
                 float* __restrict__ gated)
{
    __shared__ float tile[32][33];
    const int b = blockIdx.z;
    const int p0 = blockIdx.x * 32;
    const int c0 = blockIdx.y * 32;
    const int tx = threadIdx.x;   // 0..31
    const int ty = threadIdx.y;   // 0..7

#pragma unroll
    for (int k = 0; k < 4; k++) {
        const int p = p0 + ty + k * 8;
        tile[ty + k * 8][tx] = y1o[((size_t)b * 1024 + p) * 256 + c0 + tx];
    }
    __syncthreads();
#pragma unroll
    for (int k = 0; k < 4; k++) {
        const int c = c0 + ty + k * 8;
        const int p = p0 + tx;
        const float z = xz[((size_t)b * 512 + 256 + c) * 1024 + p];
        const float sz = z / (1.f + __expf(-z));
        gated[((size_t)b * 256 + c) * 1024 + p] = tile[tx][ty + k * 8] * sz;
    }
}

// ---------------------------------------------------------------------------
// Launcher
// ---------------------------------------------------------------------------
extern "C" void kernel_launch(void* const* d_in, const int* in_sizes, int n_in,
                              void* d_out, int out_size)
{
    const float* input_f = (const float*)d_in[0];
    const float* in_w    = (const float*)d_in[1];
    const float* in_b    = (const float*)d_in[2];
    const float* c1_w    = (const float*)d_in[3];
    const float* c1_b    = (const float*)d_in[4];
    const float* c2_w    = (const float*)d_in[5];
    const float* c2_b    = (const float*)d_in[6];
    const float* c3_w    = (const float*)d_in[7];
    const float* c3_b    = (const float*)d_in[8];
    const float* out_w   = (const float*)d_in[9];
    const float* out_b   = (const float*)d_in[10];
    const float* xw1  = (const float*)d_in[11];
    const float* dtw1 = (const float*)d_in[12];
    const float* dtb1 = (const float*)d_in[13];
    const float* Al1  = (const float*)d_in[14];
    const float* Dv1  = (const float*)d_in[15];
    const float* g1   = (const float*)d_in[16];
    const float* be1  = (const float*)d_in[17];
    const float* xw2  = (const float*)d_in[18];
    const float* dtw2 = (const float*)d_in[19];
    const float* dtb2 = (const float*)d_in[20];
    const float* Al2  = (const float*)d_in[21];
    const float* Dv2  = (const float*)d_in[22];
    const float* g2   = (const float*)d_in[23];
    const float* be2  = (const float*)d_in[24];
    const float* xw3  = (const float*)d_in[25];
    const float* dtw3 = (const float*)d_in[26];
    const float* dtb3 = (const float*)d_in[27];
    const float* Al3  = (const float*)d_in[28];
    const float* Dv3  = (const float*)d_in[29];
    const float* g3   = (const float*)d_in[30];
    const float* be3  = (const float*)d_in[31];
    (void)in_sizes; (void)n_in; (void)out_size;

    float* scratch = nullptr;
    cudaGetSymbolAddress((void**)&scratch, g_scratch);

    float* xz    = scratch + OFF_XZ;
    float* f1    = scratch + OFF_F1;
    float* f2    = scratch + OFF_F2;
    float* f3    = scratch + OFF_F3;
    float* col2  = scratch + OFF_COL2;
    float* col3  = scratch + OFF_COL3;
    float* xd1ab = scratch + OFF_XD1AB;
    float* xd2   = scratch + OFF_XD2;
    float* xd3   = scratch + OFF_XD3;
    float* wcat  = scratch + OFF_WCAT;
    float* yf1   = scratch + OFF_YF1;
    float* yr1   = scratch + OFF_YR1;
    float* yf2   = scratch + OFF_YF2;
    float* yr2   = scratch + OFF_YR2;
    float* yf3   = scratch + OFF_YF3;
    float* yr3   = scratch + OFF_YR3;
    float* y3o   = scratch + OFF_Y3O;
    float* y2o   = scratch + OFF_Y2O;
    float* y1o   = scratch + OFF_Y1O;
    float* gated = scratch + OFF_GATED;
    float* outp  = (float*)d_out;

    // 0) weight concat for merged level-1 xd projection
    wcat_k<<<(80 * 256 + 255) / 256, 256>>>(xw1, xw2, wcat);

    // 1) in-projection: xz[b][o][p], M=512,N=1024,K=512 -> 1024 blocks
    sgemm64_kernel<<<dim3(16, 8, BATCH), 128>>>(in_w, input_f, xz, in_b,
        512, 1024, 512, 512, 1024, 512LL * 1024, 512LL * 1024, 1024, 1, 1);

    // 2) c1: f1 = conv1x1(x): M=256,N=1024,K=256 -> 512 blocks
    sgemm64_kernel<<<dim3(16, 4, BATCH), 128>>>(c1_w, xz, f1, c1_b,
        256, 1024, 256, 256, 1024, 512LL * 1024, 256LL * 1024, 1024, 1, 1);

    // 3) f2 = conv2s2(f1): im2col + split-K(4) GEMM -> 512 blocks
    im2col_k<<<(BATCH * 256 * 4 * 256 + 255) / 256, 256>>>(f1, col2, 256, 32, 32);
    biasinit_k<<<(BATCH * 256 * 256 + 255) / 256, 256>>>(f2, c2_b, 256, 256,
                                                         BATCH * 256 * 256);
    sgemm64_kernel<<<dim3(4, 4, BATCH * 4), 128>>>(c2_w, col2, f2, nullptr,
        256, 256, 1024, 1024, 256, 1024LL * 256, 256LL * 256, 256, 1, 4);

    // 4) f3 = conv2s2(f2): split-K(8) -> 256 blocks
    im2col_k<<<(BATCH * 256 * 4 * 64 + 255) / 256, 256>>>(f2, col3, 256, 16, 16);
    biasinit_k<<<(BATCH * 256 * 64 + 255) / 256, 256>>>(f3, c3_b, 256, 64,
                                                        BATCH * 256 * 64);
    sgemm64_kernel<<<dim3(1, 4, BATCH * 8), 128>>>(c3_w, col3, f3, nullptr,
        256, 64, 1024, 1024, 64, 1024LL * 64, 256LL * 64, 64, 1, 8);

    // 5) xd projections
    // merged level-1: M=80 (xw1|xw2), N=1024 -> [b][L][80], 256 blocks
    sgemm64_kernel<<<dim3(16, 2, BATCH), 128>>>(wcat, f1, xd1ab, nullptr,
        80, 1024, 256, 256, 1024, 256LL * 1024, 1024LL * 80, 1, 80, 1);
    // level-2: split-K(4) -> 128 blocks
    biasinit_k<<<(BATCH * 256 * 40 + 255) / 256, 256>>>(xd2, nullptr, 40, 1,
                                                        BATCH * 256 * 40);
    sgemm64_kernel<<<dim3(4, 1, BATCH * 4), 128>>>(xw2, f2, xd2, nullptr,
        40, 256, 256, 256, 256, 256LL * 256, 256LL * 40, 1, 40, 4);
    // level-3: split-K(4) -> 32 blocks
    biasinit_k<<<(BATCH * 64 * 40 + 255) / 256, 256>>>(xd3, nullptr, 40, 1,
                                                       BATCH * 64 * 40);
    sgemm64_kernel<<<dim3(1, 1, BATCH * 4), 128>>>(xw3, f3, xd3, nullptr,
        40, 64, 256, 256, 64, 256LL * 64, 64LL * 40, 1, 40, 4);

    // 6) all six selective scans in one launch
    ScanArgs sa;
    sa.c[0] = {f1, xd1ab,      yf1, dtw1, dtb1, Al1, Dv1, L1, 0, 80};  // L1 fwd (params1)
    sa.c[1] = {f1, xd1ab + 40, yr1, dtw2, dtb2, Al2, Dv2, L1, 1, 80};  // L1 rev (params2! ref quirk)
    sa.c[2] = {f2, xd2,        yf2, dtw2, dtb2, Al2, Dv2, L2, 0, 40};
    sa.c[3] = {f2, xd2,        yr2, dtw2, dtb2, Al2, Dv2, L2, 1, 40};
    sa.c[4] = {f3, xd3,        yf3, dtw3, dtb3, Al3, Dv3, L3, 0, 40};
    sa.c[5] = {f3, xd3,        yr3, dtw3, dtb3, Al3, Dv3, L3, 1, 40};
    scan_kernel<<<dim3(16, 6), 128>>>(sa);

    // 7) combine (LayerNorm per direction + sum + upsample-add), bottom-up
    combine_kernel<<<BATCH * L3, 256>>>(yf3, yr3, g3, be3, g3, be3,
                                        (const float*)nullptr, y3o, L3, 8);
    combine_kernel<<<BATCH * L2, 256>>>(yf2, yr2, g2, be2, g2, be2,
                                        y3o, y2o, L2, 16);
    combine_kernel<<<BATCH * L1, 256>>>(yf1, yr1, g1, be1, g2, be2,
                                        y2o, y1o, L1, 32);

    // 8) gate with silu(z) + transpose to [b][c][p]
    gate_kernel<<<dim3(32, 8, BATCH), dim3(32, 8)>>>(y1o, xz, gated);

    // 9) out-projection straight into d_out: M=512,N=1024,K=256 -> 1024 blocks
    sgemm64_kernel<<<dim3(16, 8, BATCH), 128>>>(out_w, gated, outp, out_b,
        512, 1024, 256, 256, 1024, 256LL * 1024, 512LL * 1024, 1024, 1, 1);
}

// round 8
// speedup vs baseline: 1.9828x; 1.2134x over previous
#include <cuda_runtime.h>
#include <math.h>
#include <stddef.h>
#include <stdint.h>

// ---------------------------------------------------------------------------
// Problem constants (fixed by the dataset)
// ---------------------------------------------------------------------------
constexpr int BATCH  = 8;
constexpr int L1 = 1024, L2 = 256, L3 = 64;

// ---------------------------------------------------------------------------
// Scratch (single __device__ buffer; no allocations anywhere)
// ---------------------------------------------------------------------------
constexpr size_t SZ_XZ    = (size_t)BATCH * 512 * 1024;
constexpr size_t SZ_F1    = (size_t)BATCH * 256 * 1024;
constexpr size_t SZ_F2    = (size_t)BATCH * 256 * 256;
constexpr size_t SZ_F3    = (size_t)BATCH * 256 * 64;
constexpr size_t SZ_COL2  = (size_t)BATCH * 1024 * 256;
constexpr size_t SZ_COL3  = (size_t)BATCH * 1024 * 64;
constexpr size_t SZ_XD1AB = (size_t)BATCH * 1024 * 80;   // merged xw1|xw2 proj
constexpr size_t SZ_XD2   = (size_t)BATCH * 256 * 40;
constexpr size_t SZ_XD3   = (size_t)BATCH * 64 * 40;
constexpr size_t SZ_WCAT  = (size_t)80 * 256;
constexpr size_t SZ_Y1    = (size_t)BATCH * 1024 * 256;
constexpr size_t SZ_Y2    = (size_t)BATCH * 256 * 256;
constexpr size_t SZ_Y3    = (size_t)BATCH * 64 * 256;

constexpr size_t OFF_XZ    = 0;
constexpr size_t OFF_F1    = OFF_XZ    + SZ_XZ;
constexpr size_t OFF_F2    = OFF_F1    + SZ_F1;
constexpr size_t OFF_F3    = OFF_F2    + SZ_F2;
constexpr size_t OFF_COL2  = OFF_F3    + SZ_F3;
constexpr size_t OFF_COL3  = OFF_COL2  + SZ_COL2;
constexpr size_t OFF_XD1AB = OFF_COL3  + SZ_COL3;
constexpr size_t OFF_XD2   = OFF_XD1AB + SZ_XD1AB;
constexpr size_t OFF_XD3   = OFF_XD2   + SZ_XD2;
constexpr size_t OFF_WCAT  = OFF_XD3   + SZ_XD3;
constexpr size_t OFF_YF1   = OFF_WCAT  + SZ_WCAT;
constexpr size_t OFF_YR1   = OFF_YF1   + SZ_Y1;
constexpr size_t OFF_YF2   = OFF_YR1   + SZ_Y1;
constexpr size_t OFF_YR2   = OFF_YF2   + SZ_Y2;
constexpr size_t OFF_YF3   = OFF_YR2   + SZ_Y2;
constexpr size_t OFF_YR3   = OFF_YF3   + SZ_Y3;
constexpr size_t OFF_Y3O   = OFF_YR3   + SZ_Y3;
constexpr size_t OFF_Y2O   = OFF_Y3O   + SZ_Y3;
constexpr size_t OFF_Y1O   = OFF_Y2O   + SZ_Y2;
constexpr size_t OFF_GATED = OFF_Y1O   + SZ_Y1;
constexpr size_t SCRATCH_TOTAL = OFF_GATED + SZ_F1;

__device__ float g_scratch[SCRATCH_TOTAL];

// ---------------------------------------------------------------------------
// tf32 helpers
// ---------------------------------------------------------------------------
__device__ __forceinline__ float f2tf(float x)
{
    uint32_t r;
    asm("cvt.rna.tf32.f32 %0, %1;" : "=r"(r) : "f"(x));
    return __uint_as_float(r);
}

__device__ __forceinline__ void mma_tf32(float* d, const uint32_t* a,
                                         const uint32_t* b)
{
    asm volatile(
        "mma.sync.aligned.m16n8k8.row.col.f32.tf32.tf32.f32 "
        "{%0,%1,%2,%3}, {%4,%5,%6,%7}, {%8,%9}, {%0,%1,%2,%3};"
        : "+f"(d[0]), "+f"(d[1]), "+f"(d[2]), "+f"(d[3])
        : "r"(a[0]), "r"(a[1]), "r"(a[2]), "r"(a[3]), "r"(b[0]), "r"(b[1]));
}

// ---------------------------------------------------------------------------
// 64x64x16 TF32 tensor-core GEMM, 128 threads (4 warps, warp tile 32x32),
// double-buffered SMEM with global->register prefetch.
//   C[m,n] = sum_k A[m,k]*B[k,n] (+bias[m])
//   A row-major [M,K] (lda, shared across batch); B row-major [K,N] (ldb),
//   batched over blockIdx.z = batch*ksplit + ks.
//   C written at Cp[m*ldcm + n*ldcn].
//   Requires N % 64 == 0, (K/ksplit) % 16 == 0, K/ksplit >= 32.
//   ksplit>1 -> partial sums via atomicAdd (C must be pre-initialized).
// SMEM layouts (bank-conflict-free for the mma fragment access pattern):
//   As: [m 0..63][k 0..15]  row stride 20 floats
//   Bs: [k 0..15][n 0..63]  row stride 72 floats
// ---------------------------------------------------------------------------
__global__ __launch_bounds__(128)
void tgemm_kernel(const float* __restrict__ A, const float* __restrict__ B,
                  float* __restrict__ C, const float* __restrict__ bias,
                  int M, int N, int K, int lda, int ldb,
                  long long strideB, long long strideC,
                  int ldcm, int ldcn, int ksplit)
{
    __shared__ float As[2][64][20];
    __shared__ float Bs[2][16][72];

    const int tid  = threadIdx.x;
    const int lane = tid & 31;
    const int warp = tid >> 5;
    const int wm = warp & 1;          // m warp offset: 32*wm
    const int wn = warp >> 1;         // n warp offset: 32*wn
    const int gp  = lane >> 2;        // groupID 0..7
    const int tig = lane & 3;         // thread-in-group 0..3

    const int batch  = blockIdx.z / ksplit;
    const int ks     = blockIdx.z % ksplit;
    const int kchunk = K / ksplit;
    const int kbeg   = ks * kchunk;
    const int kend   = kbeg + kchunk;
    const int m0 = blockIdx.y * 64;
    const int n0 = blockIdx.x * 64;

    const float* Bp = B + (size_t)batch * (size_t)strideB;
    float* Cp = C + (size_t)batch * (size_t)strideC;

    // global-load assignments
    const int arow = tid >> 1;        // 0..63  (m)
    const int acol = (tid & 1) * 8;   // 0/8    (k)
    const int brow = tid >> 3;        // 0..15  (k)
    const int bcol = (tid & 7) * 8;   // 0..56  (n)
    const bool aval = (m0 + arow) < M;
    const float* aptr = A + (size_t)(m0 + arow) * lda + acol;
    const float* bptr = Bp + (size_t)brow * ldb + n0 + bcol;

    float acc[2][4][4];
#pragma unroll
    for (int mt = 0; mt < 2; mt++)
#pragma unroll
        for (int nt = 0; nt < 4; nt++)
#pragma unroll
            for (int r = 0; r < 4; r++) acc[mt][nt][r] = 0.f;

    float apf[8], bpf[8];

    // ---- prefetch tile 0 ----
    if (aval) {
        float4 a0 = *reinterpret_cast<const float4*>(aptr + kbeg);
        float4 a1 = *reinterpret_cast<const float4*>(aptr + kbeg + 4);
        apf[0]=a0.x; apf[1]=a0.y; apf[2]=a0.z; apf[3]=a0.w;
        apf[4]=a1.x; apf[5]=a1.y; apf[6]=a1.z; apf[7]=a1.w;
    } else {
#pragma unroll
        for (int i = 0; i < 8; i++) apf[i] = 0.f;
    }
    {
        const float* bp = bptr + (size_t)kbeg * ldb;
        float4 b0 = *reinterpret_cast<const float4*>(bp);
        float4 b1 = *reinterpret_cast<const float4*>(bp + 4);
        bpf[0]=b0.x; bpf[1]=b0.y; bpf[2]=b0.z; bpf[3]=b0.w;
        bpf[4]=b1.x; bpf[5]=b1.y; bpf[6]=b1.z; bpf[7]=b1.w;
    }
#pragma unroll
    for (int i = 0; i < 8; i++) As[0][arow][acol + i] = f2tf(apf[i]);
#pragma unroll
    for (int i = 0; i < 8; i++) Bs[0][brow][bcol + i] = f2tf(bpf[i]);
    __syncthreads();

    int cur = 0;
    for (int k0 = kbeg + 16; k0 < kend; k0 += 16) {
        // prefetch next K-tile into registers
        if (aval) {
            float4 a0 = *reinterpret_cast<const float4*>(aptr + k0);
            float4 a1 = *reinterpret_cast<const float4*>(aptr + k0 + 4);
            apf[0]=a0.x; apf[1]=a0.y; apf[2]=a0.z; apf[3]=a0.w;
            apf[4]=a1.x; apf[5]=a1.y; apf[6]=a1.z; apf[7]=a1.w;
        }
        {
            const float* bp = bptr + (size_t)k0 * ldb;
            float4 b0 = *reinterpret_cast<const float4*>(bp);
            float4 b1 = *reinterpret_cast<const float4*>(bp + 4);
            bpf[0]=b0.x; bpf[1]=b0.y; bpf[2]=b0.z; bpf[3]=b0.w;
            bpf[4]=b1.x; bpf[5]=b1.y; bpf[6]=b1.z; bpf[7]=b1.w;
        }

        // ---- mma over current buffer: 2 k8-steps ----
#pragma unroll
        for (int s = 0; s < 2; s++) {
            uint32_t af[2][4];
#pragma unroll
            for (int mt = 0; mt < 2; mt++) {
                const int mb = wm * 32 + mt * 16;
                af[mt][0] = __float_as_uint(As[cur][mb + gp    ][s*8 + tig    ]);
                af[mt][1] = __float_as_uint(As[cur][mb + gp + 8][s*8 + tig    ]);
                af[mt][2] = __float_as_uint(As[cur][mb + gp    ][s*8 + tig + 4]);
                af[mt][3] = __float_as_uint(As[cur][mb + gp + 8][s*8 + tig + 4]);
            }
            uint32_t bf[4][2];
#pragma unroll
            for (int nt = 0; nt < 4; nt++) {
                const int nb = wn * 32 + nt * 8;
                bf[nt][0] = __float_as_uint(Bs[cur][s*8 + tig    ][nb + gp]);
                bf[nt][1] = __float_as_uint(Bs[cur][s*8 + tig + 4][nb + gp]);
            }
#pragma unroll
            for (int mt = 0; mt < 2; mt++)
#pragma unroll
                for (int nt = 0; nt < 4; nt++)
                    mma_tf32(acc[mt][nt], af[mt], bf[nt]);
        }

        // store prefetched tile into the other buffer
        const int nxt = cur ^ 1;
#pragma unroll
        for (int i = 0; i < 8; i++) As[nxt][arow][acol + i] = f2tf(apf[i]);
#pragma unroll
        for (int i = 0; i < 8; i++) Bs[nxt][brow][bcol + i] = f2tf(bpf[i]);
        __syncthreads();
        cur = nxt;
    }

    // ---- final tile ----
#pragma unroll
    for (int s = 0; s < 2; s++) {
        uint32_t af[2][4];
#pragma unroll
        for (int mt = 0; mt < 2; mt++) {
            const int mb = wm * 32 + mt * 16;
            af[mt][0] = __float_as_uint(As[cur][mb + gp    ][s*8 + tig    ]);
            af[mt][1] = __float_as_uint(As[cur][mb + gp + 8][s*8 + tig    ]);
            af[mt][2] = __float_as_uint(As[cur][mb + gp    ][s*8 + tig + 4]);
            af[mt][3] = __float_as_uint(As[cur][mb + gp + 8][s*8 + tig + 4]);
        }
        uint32_t bf[4][2];
#pragma unroll
        for (int nt = 0; nt < 4; nt++) {
            const int nb = wn * 32 + nt * 8;
            bf[nt][0] = __float_as_uint(Bs[cur][s*8 + tig    ][nb + gp]);
            bf[nt][1] = __float_as_uint(Bs[cur][s*8 + tig + 4][nb + gp]);
        }
#pragma unroll
        for (int mt = 0; mt < 2; mt++)
#pragma unroll
            for (int nt = 0; nt < 4; nt++)
                mma_tf32(acc[mt][nt], af[mt], bf[nt]);
    }

    // ---- epilogue ----
#pragma unroll
    for (int mt = 0; mt < 2; mt++) {
        const int r0 = m0 + wm * 32 + mt * 16 + gp;
        const int r1 = r0 + 8;
#pragma unroll
        for (int nt = 0; nt < 4; nt++) {
            const int col = n0 + wn * 32 + nt * 8 + 2 * tig;
            if (ksplit == 1) {
                if (r0 < M) {
                    const float bv = bias ? bias[r0] : 0.f;
                    Cp[(size_t)r0 * ldcm + (size_t)col * ldcn]       = acc[mt][nt][0] + bv;
                    Cp[(size_t)r0 * ldcm + (size_t)(col + 1) * ldcn] = acc[mt][nt][1] + bv;
                }
                if (r1 < M) {
                    const float bv = bias ? bias[r1] : 0.f;
                    Cp[(size_t)r1 * ldcm + (size_t)col * ldcn]       = acc[mt][nt][2] + bv;
                    Cp[(size_t)r1 * ldcm + (size_t)(col + 1) * ldcn] = acc[mt][nt][3] + bv;
                }
            } else {
                if (r0 < M) {
                    atomicAdd(&Cp[(size_t)r0 * ldcm + (size_t)col * ldcn],       acc[mt][nt][0]);
                    atomicAdd(&Cp[(size_t)r0 * ldcm + (size_t)(col + 1) * ldcn], acc[mt][nt][1]);
                }
                if (r1 < M) {
                    atomicAdd(&Cp[(size_t)r1 * ldcm + (size_t)col * ldcn],       acc[mt][nt][2]);
                    atomicAdd(&Cp[(size_t)r1 * ldcm + (size_t)(col + 1) * ldcn], acc[mt][nt][3]);
                }
            }
        }
    }
}

// ---------------------------------------------------------------------------
// init for split-K targets: C[b][m][n] = bias ? bias[m] : 0
// ---------------------------------------------------------------------------
__global__ void biasinit_k(float* __restrict__ C, const float* __restrict__ bias,
                           int M, int N, int total)
{
    const int idx = blockIdx.x * blockDim.x + threadIdx.x;
    if (idx >= total) return;
    const int m = (idx / N) % M;
    C[idx] = bias ? bias[m] : 0.f;
}

// concat xw1 (40x256) and xw2 (40x256) -> wcat (80x256)
__global__ void wcat_k(const float* __restrict__ w1, const float* __restrict__ w2,
                       float* __restrict__ dst)
{
    const int idx = blockIdx.x * blockDim.x + threadIdx.x;
    if (idx >= 80 * 256) return;
    dst[idx] = (idx < 40 * 256) ? w1[idx] : w2[idx - 40 * 256];
}

// ---------------------------------------------------------------------------
// im2col for 2x2/stride-2 conv: src [B][C][Hs][Ws] -> dst [B][C*4][Ho*Wo]
// ---------------------------------------------------------------------------
__global__ void im2col_k(const float* __restrict__ src, float* __restrict__ dst,
                         int C, int Hs, int Ws)
{
    const int Ho = Hs >> 1, Wo = Ws >> 1;
    const int P = Ho * Wo;
    const int nTot = BATCH * C * 4 * P;
    const int idx = blockIdx.x * blockDim.x + threadIdx.x;
    if (idx >= nTot) return;
    const int n = idx % P;
    const int k = (idx / P) % (C * 4);
    const int b = idx / (P * C * 4);
    const int c = k >> 2;
    const int i = (k >> 1) & 1;
    const int j = k & 1;
    const int h = n / Wo;
    const int w = n % Wo;
    dst[idx] = src[(((size_t)b * C + c) * Hs + 2 * h + i) * Ws + 2 * w + j];
}

// ---------------------------------------------------------------------------
// Selective-scan kernel: 6 scans in one launch (blockIdx.y = scan id).
// One thread per (b,d). xd layout [b][L][pitch] (dts|Bs|Cs at given base).
// x layout [b][d][L]. dir=1 reads & writes at L-1-t => buffer holds
// flip(ssm(flip(x))) directly (LayerNorm commutes with flip).
// ---------------------------------------------------------------------------
struct ScanCfg {
    const float* x;
    const float* xd;
    float* y;
    const float* dtw;
    const float* dtb;
    const float* Al;
    const float* Dv;
    int L;
    int dir;
    int pitch;
};
struct ScanArgs { ScanCfg c[6]; };

__global__ __launch_bounds__(128)
void scan_kernel(ScanArgs args)
{
    const ScanCfg cfg = args.c[blockIdx.y];
    const int gid = blockIdx.x * 128 + threadIdx.x;   // 0..2047
    const int b = gid >> 8;
    const int d = gid & 255;
    const int L = cfg.L;
    const int dir = cfg.dir;
    const int pitch = cfg.pitch;

    float dtw_r[8];
#pragma unroll
    for (int i = 0; i < 8; i++) dtw_r[i] = cfg.dtw[d * 8 + i];
    const float dtb_r = cfg.dtb[d];
    const float Dv_r  = cfg.Dv[d];

    float A_r[16];
    bool pw = true;
#pragma unroll
    for (int n = 0; n < 16; n++) {
        A_r[n] = -expf(cfg.Al[d * 16 + n]);
        pw = pw && (fabsf(A_r[n] + (float)(n + 1)) <= 1e-4f * (float)(n + 1));
    }

    const float* xrow = cfg.x + ((size_t)b * 256 + d) * (size_t)L;
    const float* xdb  = cfg.xd + (size_t)b * L * pitch;
    float* yb = cfg.y + (size_t)b * L * 256 + d;

    float h[16];
#pragma unroll
    for (int n = 0; n < 16; n++) h[n] = 0.f;

    if (pw) {
        // A[d][n] == -(n+1): one exp per step, powers via multiply tree.
        for (int t = 0; t < L; t++) {
            const int l = dir ? (L - 1 - t) : t;
            const float4* q = reinterpret_cast<const float4*>(xdb + (size_t)l * pitch);
            const float4 d0 = q[0], d1 = q[1];
            const float4 B0 = q[2], B1 = q[3], B2 = q[4], B3 = q[5];
            const float4 C0 = q[6], C1 = q[7], C2 = q[8], C3 = q[9];
            float pre = dtb_r
                + d0.x * dtw_r[0] + d0.y * dtw_r[1] + d0.z * dtw_r[2] + d0.w * dtw_r[3]
                + d1.x * dtw_r[4] + d1.y * dtw_r[5] + d1.z * dtw_r[6] + d1.w * dtw_r[7];
            const float delta = (pre > 20.f) ? pre : log1pf(__expf(pre));
            const float xv = xrow[l];
            const float dx = delta * xv;
            const float p1 = __expf(-delta);
            const float p2 = p1 * p1, p3 = p2 * p1, p4 = p2 * p2;
            const float p5 = p4 * p1, p6 = p4 * p2, p7 = p4 * p3, p8 = p4 * p4;
            const float p9 = p8 * p1, p10 = p8 * p2, p11 = p8 * p3, p12 = p8 * p4;
            const float p13 = p8 * p5, p14 = p8 * p6, p15 = p8 * p7, p16 = p8 * p8;
            const float rr[16] = {p1,p2,p3,p4,p5,p6,p7,p8,p9,p10,p11,p12,p13,p14,p15,p16};
            const float Bv[16] = {B0.x,B0.y,B0.z,B0.w,B1.x,B1.y,B1.z,B1.w,
                                  B2.x,B2.y,B2.z,B2.w,B3.x,B3.y,B3.z,B3.w};
            const float Cv[16] = {C0.x,C0.y,C0.z,C0.w,C1.x,C1.y,C1.z,C1.w,
                                  C2.x,C2.y,C2.z,C2.w,C3.x,C3.y,C3.z,C3.w};
            float yacc = xv * Dv_r;
#pragma unroll
            for (int n = 0; n < 16; n++) {
                h[n] = h[n] * rr[n] + dx * Bv[n];
                yacc += h[n] * Cv[n];
            }
            yb[(size_t)l * 256] = yacc;
        }
    } else {
        // General path (data-independent correctness guarantee).
        for (int t = 0; t < L; t++) {
            const int l = dir ? (L - 1 - t) : t;
            const float4* q = reinterpret_cast<const float4*>(xdb + (size_t)l * pitch);
            const float4 d0 = q[0], d1 = q[1];
            const float4 B0 = q[2], B1 = q[3], B2 = q[4], B3 = q[5];
            const float4 C0 = q[6], C1 = q[7], C2 = q[8], C3 = q[9];
            float pre = dtb_r
                + d0.x * dtw_r[0] + d0.y * dtw_r[1] + d0.z * dtw_r[2] + d0.w * dtw_r[3]
                + d1.x * dtw_r[4] + d1.y * dtw_r[5] + d1.z * dtw_r[6] + d1.w * dtw_r[7];
            const float delta = (pre > 20.f) ? pre : log1pf(__expf(pre));
            const float xv = xrow[l];
            const float dx = delta * xv;
            const float Bv[16] = {B0.x,B0.y,B0.z,B0.w,B1.x,B1.y,B1.z,B1.w,
                                  B2.x,B2.y,B2.z,B2.w,B3.x,B3.y,B3.z,B3.w};
            const float Cv[16] = {C0.x,C0.y,C0.z,C0.w,C1.x,C1.y,C1.z,C1.w,
                                  C2.x,C2.y,C2.z,C2.w,C3.x,C3.y,C3.z,C3.w};
            float yacc = xv * Dv_r;
#pragma unroll
            for (int n = 0; n < 16; n++) {
                h[n] = h[n] * __expf(delta * A_r[n]) + dx * Bv[n];
                yacc += h[n] * Cv[n];
            }
            yb[(size_t)l * 256] = yacc;
        }
    }
}

// ---------------------------------------------------------------------------
// Combine: out[b,l,:] = LN(yf)*gf+bef + LN(yr)*gr+ber + up2(src)
// ---------------------------------------------------------------------------
__device__ __forceinline__ float4 warpReduce4(float4 v)
{
#pragma unroll
    for (int o = 16; o > 0; o >>= 1) {
        v.x += __shfl_xor_sync(0xffffffffu, v.x, o);
        v.y += __shfl_xor_sync(0xffffffffu, v.y, o);
        v.z += __shfl_xor_sync(0xffffffffu, v.z, o);
        v.w += __shfl_xor_sync(0xffffffffu, v.w, o);
    }
    return v;
}

__global__ __launch_bounds__(256)
void combine_kernel(const float* __restrict__ yf, const float* __restrict__ yr,
                    const float* __restrict__ gf, const float* __restrict__ bef,
                    const float* __restrict__ gr, const float* __restrict__ ber,
                    const float* __restrict__ up, float* __restrict__ out,
                    int L, int wgrid)
{
    __shared__ float4 red[8];
    const int bl = blockIdx.x;              // b*L + l
    const int d  = threadIdx.x;             // 0..255
    const size_t base = (size_t)bl * 256;

    const float vf = yf[base + d];
    const float vr = yr[base + d];

    float4 s = warpReduce4(make_float4(vf, vf * vf, vr, vr * vr));
    const int warp = threadIdx.x >> 5;
    const int lane = threadIdx.x & 31;
    if (lane == 0) red[warp] = s;
    __syncthreads();
    if (warp == 0) {
        float4 t = (lane < 8) ? red[lane] : make_float4(0.f, 0.f, 0.f, 0.f);
#pragma unroll
        for (int o = 4; o > 0; o >>= 1) {
            t.x += __shfl_xor_sync(0xffffffffu, t.x, o);
            t.y += __shfl_xor_sync(0xffffffffu, t.y, o);
            t.z += __shfl_xor_sync(0xffffffffu, t.z, o);
            t.w += __shfl_xor_sync(0xffffffffu, t.w, o);
        }
        if (lane == 0) red[0] = t;
    }
    __syncthreads();
    const float4 tot = red[0];

    const float inv = 1.f / 256.f;
    const float muf = tot.x * inv;
    const float varf = tot.y * inv - muf * muf;
    const float mur = tot.z * inv;
    const float varr = tot.w * inv - mur * mur;

    const float of = (vf - muf) * rsqrtf(varf + 1e-5f) * gf[d] + bef[d];
    const float orr = (vr - mur) * rsqrtf(varr + 1e-5f) * gr[d] + ber[d];

    float u = 0.f;
    if (up) {
        const int b = bl / L, l = bl % L;
        const int hh = l / wgrid, ww = l % wgrid;
        const int lsrc = (hh >> 1) * (wgrid >> 1) + (ww >> 1);
        u = up[((size_t)b * (L >> 2) + lsrc) * 256 + d];
    }
    out[base + d] = of + orr + u;
}

// ---------------------------------------------------------------------------
// Gate: gated[b][c][p] = y1o[b][p][c] * silu(xz[b][256+c][p])
// ---------------------------------------------------------------------------
__global__ __launch_bounds__(256)
void gate_kernel(const float* __restrict__ y1o, const float* __restrict__ xz,
                 float* __restrict__ gated)
{
    __shared__ float tile[32][33];
    const int b = blockIdx.z;
    const int p0 = blockIdx.x * 32;
    const int c0 = blockIdx.y * 32;
    const int tx = threadIdx.x;   // 0..31
    const int ty = threadIdx.y;   // 0..7

#pragma unroll
    for (int k = 0; k < 4; k++) {
        const int p = p0 + ty + k * 8;
        tile[ty + k * 8][tx] = y1o[((size_t)b * 1024 + p) * 256 + c0 + tx];
    }
    __syncthreads();
#pragma unroll
    for (int k = 0; k < 4; k++) {
        const int c = c0 + ty + k * 8;
        const int p = p0 + tx;
        const float z = xz[((size_t)b * 512 + 256 + c) * 1024 + p];
        const float sz = z / (1.f + __expf(-z));
        gated[((size_t)b * 256 + c) * 1024 + p] = tile[tx][ty + k * 8] * sz;
    }
}

// ---------------------------------------------------------------------------
// Launcher
// ---------------------------------------------------------------------------
extern "C" void kernel_launch(void* const* d_in, const int* in_sizes, int n_in,
                              void* d_out, int out_size)
{
    const float* input_f = (const float*)d_in[0];
    const float* in_w    = (const float*)d_in[1];
    const float* in_b    = (const float*)d_in[2];
    const float* c1_w    = (const float*)d_in[3];
    const float* c1_b    = (const float*)d_in[4];
    const float* c2_w    = (const float*)d_in[5];
    const float* c2_b    = (const float*)d_in[6];
    const float* c3_w    = (const float*)d_in[7];
    const float* c3_b    = (const float*)d_in[8];
    const float* out_w   = (const float*)d_in[9];
    const float* out_b   = (const float*)d_in[10];
    const float* xw1  = (const float*)d_in[11];
    const float* dtw1 = (const float*)d_in[12];
    const float* dtb1 = (const float*)d_in[13];
    const float* Al1  = (const float*)d_in[14];
    const float* Dv1  = (const float*)d_in[15];
    const float* g1   = (const float*)d_in[16];
    const float* be1  = (const float*)d_in[17];
    const float* xw2  = (const float*)d_in[18];
    const float* dtw2 = (const float*)d_in[19];
    const float* dtb2 = (const float*)d_in[20];
    const float* Al2  = (const float*)d_in[21];
    const float* Dv2  = (const float*)d_in[22];
    const float* g2   = (const float*)d_in[23];
    const float* be2  = (const float*)d_in[24];
    const float* xw3  = (const float*)d_in[25];
    const float* dtw3 = (const float*)d_in[26];
    const float* dtb3 = (const float*)d_in[27];
    const float* Al3  = (const float*)d_in[28];
    const float* Dv3  = (const float*)d_in[29];
    const float* g3   = (const float*)d_in[30];
    const float* be3  = (const float*)d_in[31];
    (void)in_sizes; (void)n_in; (void)out_size;

    float* scratch = nullptr;
    cudaGetSymbolAddress((void**)&scratch, g_scratch);

    float* xz    = scratch + OFF_XZ;
    float* f1    = scratch + OFF_F1;
    float* f2    = scratch + OFF_F2;
    float* f3    = scratch + OFF_F3;
    float* col2  = scratch + OFF_COL2;
    float* col3  = scratch + OFF_COL3;
    float* xd1ab = scratch + OFF_XD1AB;
    float* xd2   = scratch + OFF_XD2;
    float* xd3   = scratch + OFF_XD3;
    float* wcat  = scratch + OFF_WCAT;
    float* yf1   = scratch + OFF_YF1;
    float* yr1   = scratch + OFF_YR1;
    float* yf2   = scratch + OFF_YF2;
    float* yr2   = scratch + OFF_YR2;
    float* yf3   = scratch + OFF_YF3;
    float* yr3   = scratch + OFF_YR3;
    float* y3o   = scratch + OFF_Y3O;
    float* y2o   = scratch + OFF_Y2O;
    float* y1o   = scratch + OFF_Y1O;
    float* gated = scratch + OFF_GATED;
    float* outp  = (float*)d_out;

    // 0) weight concat for merged level-1 xd projection
    wcat_k<<<(80 * 256 + 255) / 256, 256>>>(xw1, xw2, wcat);

    // 1) in-projection: xz[b][o][p], M=512,N=1024,K=512 -> 1024 blocks
    tgemm_kernel<<<dim3(16, 8, BATCH), 128>>>(in_w, input_f, xz, in_b,
        512, 1024, 512, 512, 1024, 512LL * 1024, 512LL * 1024, 1024, 1, 1);

    // 2) c1: f1 = conv1x1(x): M=256,N=1024,K=256 -> 512 blocks
    tgemm_kernel<<<dim3(16, 4, BATCH), 128>>>(c1_w, xz, f1, c1_b,
        256, 1024, 256, 256, 1024, 512LL * 1024, 256LL * 1024, 1024, 1, 1);

    // 3) f2 = conv2s2(f1): im2col + split-K(4) GEMM -> 512 blocks
    im2col_k<<<(BATCH * 256 * 4 * 256 + 255) / 256, 256>>>(f1, col2, 256, 32, 32);
    biasinit_k<<<(BATCH * 256 * 256 + 255) / 256, 256>>>(f2, c2_b, 256, 256,
                                                         BATCH * 256 * 256);
    tgemm_kernel<<<dim3(4, 4, BATCH * 4), 128>>>(c2_w, col2, f2, nullptr,
        256, 256, 1024, 1024, 256, 1024LL * 256, 256LL * 256, 256, 1, 4);

    // 4) f3 = conv2s2(f2): split-K(8) -> 256 blocks
    im2col_k<<<(BATCH * 256 * 4 * 64 + 255) / 256, 256>>>(f2, col3, 256, 16, 16);
    biasinit_k<<<(BATCH * 256 * 64 + 255) / 256, 256>>>(f3, c3_b, 256, 64,
                                                        BATCH * 256 * 64);
    tgemm_kernel<<<dim3(1, 4, BATCH * 8), 128>>>(c3_w, col3, f3, nullptr,
        256, 64, 1024, 1024, 64, 1024LL * 64, 256LL * 64, 64, 1, 8);

    // 5) xd projections
    // merged level-1: M=80 (xw1|xw2), N=1024 -> [b][L][80], 256 blocks
    tgemm_kernel<<<dim3(16, 2, BATCH), 128>>>(wcat, f1, xd1ab, nullptr,
        80, 1024, 256, 256, 1024, 256LL * 1024, 1024LL * 80, 1, 80, 1);
    // level-2: split-K(4) -> 128 blocks
    biasinit_k<<<(BATCH * 256 * 40 + 255) / 256, 256>>>(xd2, nullptr, 40, 1,
                                                        BATCH * 256 * 40);
    tgemm_kernel<<<dim3(4, 1, BATCH * 4), 128>>>(xw2, f2, xd2, nullptr,
        40, 256, 256, 256, 256, 256LL * 256, 256LL * 40, 1, 40, 4);
    // level-3: split-K(4) -> 32 blocks
    biasinit_k<<<(BATCH * 64 * 40 + 255) / 256, 256>>>(xd3, nullptr, 40, 1,
                                                       BATCH * 64 * 40);
    tgemm_kernel<<<dim3(1, 1, BATCH * 4), 128>>>(xw3, f3, xd3, nullptr,
        40, 64, 256, 256, 64, 256LL * 64, 64LL * 40, 1, 40, 4);

    // 6) all six selective scans in one launch
    ScanArgs sa;
    sa.c[0] = {f1, xd1ab,      yf1, dtw1, dtb1, Al1, Dv1, L1, 0, 80};  // L1 fwd (params1)
    sa.c[1] = {f1, xd1ab + 40, yr1, dtw2, dtb2, Al2, Dv2, L1, 1, 80};  // L1 rev (params2! ref quirk)
    sa.c[2] = {f2, xd2,        yf2, dtw2, dtb2, Al2, Dv2, L2, 0, 40};
    sa.c[3] = {f2, xd2,        yr2, dtw2, dtb2, Al2, Dv2, L2, 1, 40};
    sa.c[4] = {f3, xd3,        yf3, dtw3, dtb3, Al3, Dv3, L3, 0, 40};
    sa.c[5] = {f3, xd3,        yr3, dtw3, dtb3, Al3, Dv3, L3, 1, 40};
    scan_kernel<<<dim3(16, 6), 128>>>(sa);

    // 7) combine (LayerNorm per direction + sum + upsample-add), bottom-up
    combine_kernel<<<BATCH * L3, 256>>>(yf3, yr3, g3, be3, g3, be3,
                                        (const float*)nullptr, y3o, L3, 8);
    combine_kernel<<<BATCH * L2, 256>>>(yf2, yr2, g2, be2, g2, be2,
                                        y3o, y2o, L2, 16);
    combine_kernel<<<BATCH * L1, 256>>>(yf1, yr1, g1, be1, g2, be2,
                                        y2o, y1o, L1, 32);

    // 8) gate with silu(z) + transpose to [b][c][p]
    gate_kernel<<<dim3(32, 8, BATCH), dim3(32, 8)>>>(y1o, xz, gated);

    // 9) out-projection straight into d_out: M=512,N=1024,K=256 -> 1024 blocks
    tgemm_kernel<<<dim3(16, 8, BATCH), 128>>>(out_w, gated, outp, out_b,
        512, 1024, 256, 256, 1024, 256LL * 1024, 512LL * 1024, 1024, 1, 1);
}